// round 11
// baseline (speedup 1.0000x reference)
#include <cuda_runtime.h>
#include <cuda_fp16.h>
#include <math.h>

#define NN 50000          // nodes
#define NE 400000         // edges (without self loops)
#define ET (NN + NE)      // total edges incl. self loops
#define NH 8              // heads
#define HC 512            // heads * channels
#define FIN 11            // input features
#define K1B ((NN + 7) / 8)                 // k1 blocks inside merged kernel
#define HISTB ((ET + 127) / 128)           // hist blocks inside merged kernel

// ---------------- scratch (static device globals; no allocation) -------------
__device__ __align__(16) __half g_hh[(size_t)NN * HC];  // layer-1 features (51 MB, fp16)
__device__ __align__(16) float g_asrc[NN * NH];
__device__ __align__(16) float g_adst[NN * NH];
__device__ int   g_cnt[NN];     // zero-initialized; re-zeroed by k_offsets each call
__device__ int   g_off[NN];
__device__ int   g_qend[NN];
__device__ int   g_cur[NN];
__device__ int   g_total;       // zero-initialized; re-zeroed by k_scatter each call
__device__ int   g_ssrc[ET];
__device__ __align__(16) uint4 g_wp[ET];   // 8 x fp16 unnormalized exp weights (7.2 MB)
__device__ float g_h2[NN];
__device__ float g_a2s[NN];
__device__ float g_a2d[NN];

__device__ __forceinline__ float lrelu(float v) { return v > 0.f ? v : 0.2f * v; }
__device__ __forceinline__ float4 f4fma(float a, float4 v, float4 acc) {
    acc.x = fmaf(a, v.x, acc.x); acc.y = fmaf(a, v.y, acc.y);
    acc.z = fmaf(a, v.z, acc.z); acc.w = fmaf(a, v.w, acc.w); return acc;
}
__device__ __forceinline__ float f4dot(float4 a, float4 b) {
    return a.x * b.x + a.y * b.y + a.z * b.z + a.w * b.w;
}
__device__ __forceinline__ int edge_at(const void* ei, int idx, int is64) {
    return is64 ? (int)((const long long*)ei)[idx] : ((const int*)ei)[idx];
}
// block-local edge dtype detection (int32 vs int64), broadcast via smem.
__device__ __forceinline__ int detect_is64(const void* ei, int nNodes, int* sflag) {
    if (threadIdx.x == 0) {
        const long long* p = (const long long*)ei;
        int ok = 1;
#pragma unroll 1
        for (int k = 0; k < 8; k++) {
            long long v = p[k];
            if (v < 0 || v >= nNodes) { ok = 0; break; }
        }
        *sflag = ok;
    }
    __syncthreads();
    return *sflag;
}
__device__ __forceinline__ void fma8(float w, uint4 v, float* acc) {
    const __half2* h = (const __half2*)&v;
#pragma unroll
    for (int k = 0; k < 4; k++) {
        float2 f = __half22float2(h[k]);
        acc[2 * k]     = fmaf(w, f.x, acc[2 * k]);
        acc[2 * k + 1] = fmaf(w, f.y, acc[2 * k + 1]);
    }
}
__device__ __forceinline__ float wext(unsigned word, int hsh) {
    return __half2float(__ushort_as_half((unsigned short)(word >> hsh)));
}

// ---------------- K1: feature transform | degree histogram (merged) ----------
__global__ void k1_hist(const float* __restrict__ x, const float* __restrict__ W1,
                        const float* __restrict__ as1, const float* __restrict__ ad1,
                        const void* __restrict__ ei, int nNodes, int nE) {
    __shared__ float sx[8][FIN];
    __shared__ int sflag;
    int t = threadIdx.x;
    if (blockIdx.x >= K1B) {                 // ---- histogram role ----
        int is64 = detect_is64(ei, nNodes, &sflag);
        int i = (blockIdx.x - K1B) * 128 + t;
        int tot = nE + nNodes;
        if (i >= tot) return;
        int d = (i < nE) ? edge_at(ei, nE + i, is64) : (i - nE);
        if ((unsigned)d >= (unsigned)nNodes) return;
        atomicAdd(&g_cnt[d], 1);
        return;
    }
    // ---- k1 role ----
    int nb = blockIdx.x * 8;
    if (t < 8 * FIN) {
        int ni = t / FIN, k = t % FIN;
        int n = nb + ni;
        sx[ni][k] = (n < nNodes) ? x[(size_t)n * FIN + k] : 0.f;
    }
    float4 w[FIN];
#pragma unroll
    for (int k = 0; k < FIN; k++) w[k] = ((const float4*)W1)[k * 128 + t];
    float4 a4 = ((const float4*)as1)[t];
    float4 d4 = ((const float4*)ad1)[t];
    __syncthreads();
    int head = t >> 4;  // 16 threads per head
#pragma unroll 1
    for (int ni = 0; ni < 8; ni++) {
        int n = nb + ni;
        if (n >= nNodes) break;
        float4 acc = {0.f, 0.f, 0.f, 0.f};
#pragma unroll
        for (int k = 0; k < FIN; k++) acc = f4fma(sx[ni][k], w[k], acc);
        union { __half2 h2[2]; uint2 u; } pk;
        pk.h2[0] = __floats2half2_rn(acc.x, acc.y);
        pk.h2[1] = __floats2half2_rn(acc.z, acc.w);
        ((uint2*)g_hh)[(size_t)n * 128 + t] = pk.u;
        float ps = f4dot(acc, a4);
        float pd = f4dot(acc, d4);
#pragma unroll
        for (int o = 8; o >= 1; o >>= 1) {
            ps += __shfl_xor_sync(0xffffffffu, ps, o);
            pd += __shfl_xor_sync(0xffffffffu, pd, o);
        }
        if ((t & 15) == 0) {
            g_asrc[n * NH + head] = ps;
            g_adst[n * NH + head] = pd;
        }
    }
}

// ---------------- K2: offsets via warp-aggregated atomic bump ----------------
__global__ void k_offsets(int nNodes) {
    int n = blockIdx.x * blockDim.x + threadIdx.x;
    int lane = threadIdx.x & 31;
    int c = (n < nNodes) ? g_cnt[n] : 0;
    int incl = c;
#pragma unroll
    for (int o = 1; o < 32; o <<= 1) {
        int v = __shfl_up_sync(0xffffffffu, incl, o);
        if (lane >= o) incl += v;
    }
    int wtot = __shfl_sync(0xffffffffu, incl, 31);
    int base = 0;
    if (lane == 31) base = atomicAdd(&g_total, wtot);
    base = __shfl_sync(0xffffffffu, base, 31);
    if (n < nNodes) {
        int start = base + incl - c;
        g_off[n]  = start;
        g_qend[n] = start + c;
        g_cur[n]  = start;
        g_cnt[n]  = 0;                       // reset for next replay
    }
}

// ---------------- K3: scatter sorted edges + packed fp16 exp scores ----------
__global__ void k_scatter(const void* __restrict__ ei, int nE, int nNodes) {
    __shared__ int sflag;
    int is64 = detect_is64(ei, nNodes, &sflag);
    if (blockIdx.x == 0 && threadIdx.x == 0) g_total = 0;   // reset for next replay
    int i = blockIdx.x * blockDim.x + threadIdx.x;
    int tot = nE + nNodes;
    if (i >= tot) return;
    int s, d;
    if (i < nE) { s = edge_at(ei, i, is64); d = edge_at(ei, nE + i, is64); }
    else        { s = d = i - nE; }
    if ((unsigned)d >= (unsigned)nNodes || (unsigned)s >= (unsigned)nNodes) return;
    int pos = atomicAdd(&g_cur[d], 1);
    g_ssrc[pos] = s;
    float4 a0 = ((const float4*)&g_asrc[s * NH])[0];
    float4 a1 = ((const float4*)&g_asrc[s * NH])[1];
    float4 d0 = ((const float4*)&g_adst[d * NH])[0];
    float4 d1 = ((const float4*)&g_adst[d * NH])[1];
    float4 e0, e1;
    e0.x = __expf(lrelu(a0.x + d0.x)); e0.y = __expf(lrelu(a0.y + d0.y));
    e0.z = __expf(lrelu(a0.z + d0.z)); e0.w = __expf(lrelu(a0.w + d0.w));
    e1.x = __expf(lrelu(a1.x + d1.x)); e1.y = __expf(lrelu(a1.y + d1.y));
    e1.z = __expf(lrelu(a1.z + d1.z)); e1.w = __expf(lrelu(a1.w + d1.w));
    union { __half2 h2[4]; uint4 u; } pk;
    pk.h2[0] = __floats2half2_rn(e0.x, e0.y);
    pk.h2[1] = __floats2half2_rn(e0.z, e0.w);
    pk.h2[2] = __floats2half2_rn(e1.x, e1.y);
    pk.h2[3] = __floats2half2_rn(e1.z, e1.w);
    g_wp[pos] = pk.u;
}

// ---------------- K4: aggregation (1 warp/node; chunked metadata) ------------
// Lane L owns channels [8L,8L+8) (head L>>3) and [256+8L,+8) (head (L>>3)+4).
// Edges processed in chunks of 32: lane j loads edge base+j's src index and
// full packed-weight uint4 (coalesced). Per edge, the RAW words are shuffled
// from lane j and each receiving lane selects its own head's half AFTER the
// shuffle (the R10 bug was selecting before the shuffle with the source
// lane's selector). Metadata: ~0.16 L1 wavefronts/edge; gather: 8/edge.
__global__ void __launch_bounds__(256, 6)
k_agg(const float* __restrict__ b1, const float* __restrict__ W2,
      const float* __restrict__ as2, const float* __restrict__ ad2,
      int nNodes) {
    int n = (blockIdx.x * blockDim.x + threadIdx.x) >> 5;
    int lane = threadIdx.x & 31;
    if (n >= nNodes) return;
    int p = g_off[n], q = g_qend[n];

    int hA   = lane >> 3;            // 0..3 (head A; head B = hA+4)
    int wsel = hA >> 1;              // which word of each pair holds my head
    int hsh  = (hA & 1) << 4;        // 0 or 16-bit shift within the word

    float accA[8], accB[8];
#pragma unroll
    for (int k = 0; k < 8; k++) { accA[k] = 0.f; accB[k] = 0.f; }
    float sA = 0.f, sB = 0.f;

#pragma unroll 1
    for (int base = p; base < q; base += 32) {
        int m = q - base;
        int cnt = m < 32 ? m : 32;
        int idx = base + (lane < cnt ? lane : cnt - 1);
        int   sn_l = g_ssrc[idx];
        uint4 wp_l = g_wp[idx];
#pragma unroll 1
        for (int j = 0; j < cnt; j++) {
            int sn      = __shfl_sync(0xffffffffu, sn_l, j);
            unsigned rx = __shfl_sync(0xffffffffu, wp_l.x, j);
            unsigned ry = __shfl_sync(0xffffffffu, wp_l.y, j);
            unsigned rz = __shfl_sync(0xffffffffu, wp_l.z, j);
            unsigned rw = __shfl_sync(0xffffffffu, wp_l.w, j);
            float wA = wext(wsel ? ry : rx, hsh);   // select with MY head
            float wB = wext(wsel ? rw : rz, hsh);
            const uint4* hr = (const uint4*)&g_hh[(size_t)sn * HC];
            uint4 vA = __ldcg(hr + lane);
            uint4 vB = __ldcg(hr + lane + 32);
            sA += wA; sB += wB;
            fma8(wA, vA, accA);
            fma8(wB, vB, accB);
        }
    }

    float iA = 1.f / (sA + 1e-16f);
    float iB = 1.f / (sB + 1e-16f);

    // epilogue: normalize, + b1, ELU, project with W2, warp-reduce -> h2 scalar
    float dot = 0.f;
#pragma unroll
    for (int k = 0; k < 8; k++) {
        float vA = fmaf(accA[k], iA, b1[8 * lane + k]);
        vA = vA > 0.f ? vA : __expf(vA) - 1.f;
        dot = fmaf(vA, W2[8 * lane + k], dot);
        float vB = fmaf(accB[k], iB, b1[256 + 8 * lane + k]);
        vB = vB > 0.f ? vB : __expf(vB) - 1.f;
        dot = fmaf(vB, W2[256 + 8 * lane + k], dot);
    }
#pragma unroll
    for (int o = 16; o; o >>= 1) dot += __shfl_xor_sync(0xffffffffu, dot, o);
    if (lane == 0) {
        g_h2[n]  = dot;
        g_a2s[n] = dot * as2[0];
        g_a2d[n] = dot * ad2[0];
    }
}

// ---------------- K5: layer-2 attention (warp per node, single pass) ---------
__global__ void k_l2(float* __restrict__ out, const float* __restrict__ b2, int nNodes) {
    int n = (blockIdx.x * blockDim.x + threadIdx.x) >> 5;
    int lane = threadIdx.x & 31;
    if (n >= nNodes) return;
    int p = g_off[n], q = g_qend[n];
    float ad = g_a2d[n];
    float sum = 0.f, acc = 0.f;
    for (int i = p + lane; i < q; i += 32) {
        int sn = g_ssrc[i];
        float v = __expf(lrelu(g_a2s[sn] + ad));
        sum += v;
        acc = fmaf(v, g_h2[sn], acc);
    }
#pragma unroll
    for (int o = 16; o; o >>= 1) {
        sum += __shfl_xor_sync(0xffffffffu, sum, o);
        acc += __shfl_xor_sync(0xffffffffu, acc, o);
    }
    if (lane == 0) out[n] = acc / (sum + 1e-16f) + b2[0];
}

// ---------------- launch -----------------------------------------------------
extern "C" void kernel_launch(void* const* d_in, const int* in_sizes, int n_in,
                              void* d_out, int out_size) {
    const float* x   = (const float*)d_in[0];
    const void*  ei  = d_in[1];
    const float* W1  = (const float*)d_in[2];
    const float* as1 = (const float*)d_in[3];
    const float* ad1 = (const float*)d_in[4];
    const float* b1  = (const float*)d_in[5];
    const float* W2  = (const float*)d_in[6];
    const float* as2 = (const float*)d_in[7];
    const float* ad2 = (const float*)d_in[8];
    const float* b2  = (const float*)d_in[9];

    int nN = in_sizes[0] / FIN;   // 50000
    int nE = in_sizes[1] / 2;     // 400000
    int tot = nN + nE;

    k1_hist  <<<K1B + HISTB, 128>>>(x, W1, as1, ad1, ei, nN, nE);
    k_offsets<<<(nN + 255) / 256, 256>>>(nN);
    k_scatter<<<(tot + 255) / 256, 256>>>(ei, nE, nN);
    k_agg    <<<(nN + 7) / 8, 256>>>(b1, W2, as2, ad2, nN);
    k_l2     <<<(nN + 7) / 8, 256>>>((float*)d_out, b2, nN);
}

// round 12
// speedup vs baseline: 1.0922x; 1.0922x over previous
#include <cuda_runtime.h>
#include <cuda_fp16.h>
#include <math.h>

#define NN 50000          // nodes
#define NE 400000         // edges (without self loops)
#define ET (NN + NE)      // total edges incl. self loops
#define NH 8              // heads
#define HC 512            // heads * channels
#define FIN 11            // input features
#define AXW (NH * FIN)    // 88 aggregated input-space values per node
#define K1B ((NN + 7) / 8)                 // k1 blocks inside merged kernel
#define HISTB ((ET + 127) / 128)           // hist blocks inside merged kernel

// ---------------- scratch (static device globals; no allocation) -------------
__device__ __align__(16) float g_asrc[NN * NH];
__device__ __align__(16) float g_adst[NN * NH];
__device__ __align__(16) float g_ax[(size_t)NN * AXW]; // aggregated x per head (17.6 MB)
__device__ int   g_cnt[NN];     // zero-initialized; re-zeroed by k_offsets each call
__device__ int   g_off[NN];
__device__ int   g_qend[NN];
__device__ int   g_cur[NN];
__device__ int   g_total;       // zero-initialized; re-zeroed by k_scatter each call
__device__ int   g_ssrc[ET];
__device__ __align__(16) uint4 g_wp[ET];   // 8 x fp16 unnormalized exp weights (7.2 MB)
__device__ float g_h2[NN];
__device__ float g_a2s[NN];
__device__ float g_a2d[NN];

__device__ __forceinline__ float lrelu(float v) { return v > 0.f ? v : 0.2f * v; }
__device__ __forceinline__ float4 f4fma(float a, float4 v, float4 acc) {
    acc.x = fmaf(a, v.x, acc.x); acc.y = fmaf(a, v.y, acc.y);
    acc.z = fmaf(a, v.z, acc.z); acc.w = fmaf(a, v.w, acc.w); return acc;
}
__device__ __forceinline__ float f4dot(float4 a, float4 b) {
    return a.x * b.x + a.y * b.y + a.z * b.z + a.w * b.w;
}
__device__ __forceinline__ int edge_at(const void* ei, int idx, int is64) {
    return is64 ? (int)((const long long*)ei)[idx] : ((const int*)ei)[idx];
}
// block-local edge dtype detection (int32 vs int64), broadcast via smem.
__device__ __forceinline__ int detect_is64(const void* ei, int nNodes, int* sflag) {
    if (threadIdx.x == 0) {
        const long long* p = (const long long*)ei;
        int ok = 1;
#pragma unroll 1
        for (int k = 0; k < 8; k++) {
            long long v = p[k];
            if (v < 0 || v >= nNodes) { ok = 0; break; }
        }
        *sflag = ok;
    }
    __syncthreads();
    return *sflag;
}

// ---------------- K1: attention scores | degree histogram (merged) -----------
// h = x@W1 is computed in registers ONLY for the attention dots; it is never
// stored (the aggregation happens in input space via linearity).
__global__ void k1_hist(const float* __restrict__ x, const float* __restrict__ W1,
                        const float* __restrict__ as1, const float* __restrict__ ad1,
                        const void* __restrict__ ei, int nNodes, int nE) {
    __shared__ float sx[8][FIN];
    __shared__ int sflag;
    int t = threadIdx.x;
    if (blockIdx.x >= K1B) {                 // ---- histogram role ----
        int is64 = detect_is64(ei, nNodes, &sflag);
        int i = (blockIdx.x - K1B) * 128 + t;
        int tot = nE + nNodes;
        if (i >= tot) return;
        int d = (i < nE) ? edge_at(ei, nE + i, is64) : (i - nE);
        if ((unsigned)d >= (unsigned)nNodes) return;
        atomicAdd(&g_cnt[d], 1);
        return;
    }
    // ---- k1 role ----
    int nb = blockIdx.x * 8;
    if (t < 8 * FIN) {
        int ni = t / FIN, k = t % FIN;
        int n = nb + ni;
        sx[ni][k] = (n < nNodes) ? x[(size_t)n * FIN + k] : 0.f;
    }
    float4 w[FIN];
#pragma unroll
    for (int k = 0; k < FIN; k++) w[k] = ((const float4*)W1)[k * 128 + t];
    float4 a4 = ((const float4*)as1)[t];
    float4 d4 = ((const float4*)ad1)[t];
    __syncthreads();
    int head = t >> 4;  // 16 threads per head
#pragma unroll 1
    for (int ni = 0; ni < 8; ni++) {
        int n = nb + ni;
        if (n >= nNodes) break;
        float4 acc = {0.f, 0.f, 0.f, 0.f};
#pragma unroll
        for (int k = 0; k < FIN; k++) acc = f4fma(sx[ni][k], w[k], acc);
        float ps = f4dot(acc, a4);
        float pd = f4dot(acc, d4);
#pragma unroll
        for (int o = 8; o >= 1; o >>= 1) {
            ps += __shfl_xor_sync(0xffffffffu, ps, o);
            pd += __shfl_xor_sync(0xffffffffu, pd, o);
        }
        if ((t & 15) == 0) {
            g_asrc[n * NH + head] = ps;
            g_adst[n * NH + head] = pd;
        }
    }
}

// ---------------- K2: offsets via warp-aggregated atomic bump ----------------
__global__ void k_offsets(int nNodes) {
    int n = blockIdx.x * blockDim.x + threadIdx.x;
    int lane = threadIdx.x & 31;
    int c = (n < nNodes) ? g_cnt[n] : 0;
    int incl = c;
#pragma unroll
    for (int o = 1; o < 32; o <<= 1) {
        int v = __shfl_up_sync(0xffffffffu, incl, o);
        if (lane >= o) incl += v;
    }
    int wtot = __shfl_sync(0xffffffffu, incl, 31);
    int base = 0;
    if (lane == 31) base = atomicAdd(&g_total, wtot);
    base = __shfl_sync(0xffffffffu, base, 31);
    if (n < nNodes) {
        int start = base + incl - c;
        g_off[n]  = start;
        g_qend[n] = start + c;
        g_cur[n]  = start;
        g_cnt[n]  = 0;                       // reset for next replay
    }
}

// ---------------- K3: scatter sorted edges + packed fp16 exp scores ----------
__global__ void k_scatter(const void* __restrict__ ei, int nE, int nNodes) {
    __shared__ int sflag;
    int is64 = detect_is64(ei, nNodes, &sflag);
    if (blockIdx.x == 0 && threadIdx.x == 0) g_total = 0;   // reset for next replay
    int i = blockIdx.x * blockDim.x + threadIdx.x;
    int tot = nE + nNodes;
    if (i >= tot) return;
    int s, d;
    if (i < nE) { s = edge_at(ei, i, is64); d = edge_at(ei, nE + i, is64); }
    else        { s = d = i - nE; }
    if ((unsigned)d >= (unsigned)nNodes || (unsigned)s >= (unsigned)nNodes) return;
    int pos = atomicAdd(&g_cur[d], 1);
    g_ssrc[pos] = s;
    float4 a0 = ((const float4*)&g_asrc[s * NH])[0];
    float4 a1 = ((const float4*)&g_asrc[s * NH])[1];
    float4 d0 = ((const float4*)&g_adst[d * NH])[0];
    float4 d1 = ((const float4*)&g_adst[d * NH])[1];
    float4 e0, e1;
    e0.x = __expf(lrelu(a0.x + d0.x)); e0.y = __expf(lrelu(a0.y + d0.y));
    e0.z = __expf(lrelu(a0.z + d0.z)); e0.w = __expf(lrelu(a0.w + d0.w));
    e1.x = __expf(lrelu(a1.x + d1.x)); e1.y = __expf(lrelu(a1.y + d1.y));
    e1.z = __expf(lrelu(a1.z + d1.z)); e1.w = __expf(lrelu(a1.w + d1.w));
    union { __half2 h2[4]; uint4 u; } pk;
    pk.h2[0] = __floats2half2_rn(e0.x, e0.y);   // wp.x = heads 0,1
    pk.h2[1] = __floats2half2_rn(e0.z, e0.w);   // wp.y = heads 2,3
    pk.h2[2] = __floats2half2_rn(e1.x, e1.y);   // wp.z = heads 4,5
    pk.h2[3] = __floats2half2_rn(e1.z, e1.w);   // wp.w = heads 6,7
    g_wp[pos] = pk.u;
}

// ---------------- K4: input-space aggregation (2 threads per node) -----------
// By linearity: sum_e w_e * (x[src_e] @ W1) = (sum_e w_e * x[src_e]) @ W1.
// Thread (2n+half) owns node n, heads [4*half, 4*half+4): 44 fp32 accumulators.
// Per edge: 16B weight uint4 + 44B x-row (fp32, exact). Both threads of a node
// sit in the same warp and read identical addresses -> wavefronts dedup.
__global__ void __launch_bounds__(128)
k_agg_x(const float* __restrict__ x, int nNodes) {
    int tid = blockIdx.x * blockDim.x + threadIdx.x;
    int n = tid >> 1;
    int half = tid & 1;
    if (n >= nNodes) return;
    int p = g_off[n], q = g_qend[n];

    float ax[4][FIN];
    float sw[4];
#pragma unroll
    for (int h = 0; h < 4; h++) {
        sw[h] = 0.f;
#pragma unroll
        for (int d = 0; d < FIN; d++) ax[h][d] = 0.f;
    }
#pragma unroll 1
    for (int i = p; i < q; i++) {
        uint4 wp = g_wp[i];
        int sn = g_ssrc[i];
        unsigned u0 = half ? wp.z : wp.x;
        unsigned u1 = half ? wp.w : wp.y;
        float2 f0 = __half22float2(*(__half2*)&u0);
        float2 f1 = __half22float2(*(__half2*)&u1);
        float w[4] = {f0.x, f0.y, f1.x, f1.y};
        const float* xr = x + (size_t)sn * FIN;
        float xv[FIN];
#pragma unroll
        for (int d = 0; d < FIN; d++) xv[d] = __ldg(xr + d);
#pragma unroll
        for (int h = 0; h < 4; h++) {
            sw[h] += w[h];
#pragma unroll
            for (int d = 0; d < FIN; d++) ax[h][d] = fmaf(w[h], xv[d], ax[h][d]);
        }
    }
    float* out = &g_ax[(size_t)n * AXW + half * 4 * FIN];
#pragma unroll
    for (int h = 0; h < 4; h++) {
        float inv = 1.f / (sw[h] + 1e-16f);
#pragma unroll
        for (int d = 0; d < FIN; d++) out[h * FIN + d] = ax[h][d] * inv;
    }
}

// ---------------- K5: per-node transform: ax@W1 + b1, ELU, dot W2 ------------
// Warp per node (8 warps/block). Lane owns channels {lane + 32k, k=0..15};
// for step k all lanes use head k>>1 (broadcast from smem, conflict-free) and
// W1 smem reads are consecutive-bank.
__global__ void k_trans(const float* __restrict__ W1, const float* __restrict__ b1,
                        const float* __restrict__ W2,
                        const float* __restrict__ as2, const float* __restrict__ ad2,
                        int nNodes) {
    __shared__ float sW1[FIN][HC];      // 22528 B
    __shared__ float sAx[8][AXW];       // 2816 B
    int t = threadIdx.x;
    for (int i = t; i < FIN * HC; i += 256) sW1[0][i] = W1[i];
    int wid = t >> 5, lane = t & 31;
    int n = blockIdx.x * 8 + wid;
    bool act = (n < nNodes);
    if (act)
        for (int i = lane; i < AXW; i += 32) sAx[wid][i] = g_ax[(size_t)n * AXW + i];
    __syncthreads();
    if (!act) return;

    float dot = 0.f;
#pragma unroll
    for (int k = 0; k < 16; k++) {
        int c = lane + 32 * k;
        int head = k >> 1;               // all lanes same head at step k
        float acc = __ldg(b1 + c);
#pragma unroll
        for (int d = 0; d < FIN; d++)
            acc = fmaf(sAx[wid][head * FIN + d], sW1[d][c], acc);
        acc = acc > 0.f ? acc : __expf(acc) - 1.f;   // ELU
        dot = fmaf(acc, __ldg(W2 + c), dot);
    }
#pragma unroll
    for (int o = 16; o; o >>= 1) dot += __shfl_xor_sync(0xffffffffu, dot, o);
    if (lane == 0) {
        g_h2[n]  = dot;
        g_a2s[n] = dot * as2[0];
        g_a2d[n] = dot * ad2[0];
    }
}

// ---------------- K6: layer-2 attention (warp per node, single pass) ---------
__global__ void k_l2(float* __restrict__ out, const float* __restrict__ b2, int nNodes) {
    int n = (blockIdx.x * blockDim.x + threadIdx.x) >> 5;
    int lane = threadIdx.x & 31;
    if (n >= nNodes) return;
    int p = g_off[n], q = g_qend[n];
    float ad = g_a2d[n];
    float sum = 0.f, acc = 0.f;
    for (int i = p + lane; i < q; i += 32) {
        int sn = g_ssrc[i];
        float v = __expf(lrelu(g_a2s[sn] + ad));
        sum += v;
        acc = fmaf(v, g_h2[sn], acc);
    }
#pragma unroll
    for (int o = 16; o; o >>= 1) {
        sum += __shfl_xor_sync(0xffffffffu, sum, o);
        acc += __shfl_xor_sync(0xffffffffu, acc, o);
    }
    if (lane == 0) out[n] = acc / (sum + 1e-16f) + b2[0];
}

// ---------------- launch -----------------------------------------------------
extern "C" void kernel_launch(void* const* d_in, const int* in_sizes, int n_in,
                              void* d_out, int out_size) {
    const float* x   = (const float*)d_in[0];
    const void*  ei  = d_in[1];
    const float* W1  = (const float*)d_in[2];
    const float* as1 = (const float*)d_in[3];
    const float* ad1 = (const float*)d_in[4];
    const float* b1  = (const float*)d_in[5];
    const float* W2  = (const float*)d_in[6];
    const float* as2 = (const float*)d_in[7];
    const float* ad2 = (const float*)d_in[8];
    const float* b2  = (const float*)d_in[9];

    int nN = in_sizes[0] / FIN;   // 50000
    int nE = in_sizes[1] / 2;     // 400000
    int tot = nN + nE;

    k1_hist  <<<K1B + HISTB, 128>>>(x, W1, as1, ad1, ei, nN, nE);
    k_offsets<<<(nN + 255) / 256, 256>>>(nN);
    k_scatter<<<(tot + 255) / 256, 256>>>(ei, nE, nN);
    k_agg_x  <<<(2 * nN + 127) / 128, 128>>>(x, nN);
    k_trans  <<<(nN + 7) / 8, 256>>>(W1, b1, W2, as2, ad2, nN);
    k_l2     <<<(nN + 7) / 8, 256>>>((float*)d_out, b2, nN);
}

// round 13
// speedup vs baseline: 1.1037x; 1.0105x over previous
#include <cuda_runtime.h>
#include <cuda_fp16.h>
#include <math.h>

#define NN 50000          // nodes
#define NE 400000         // edges (without self loops)
#define ET (NN + NE)      // total edges incl. self loops
#define NH 8              // heads
#define HC 512            // heads * channels
#define FIN 11            // input features
#define AXP 96            // padded aggregated row: 8 heads x 12 (11 + pad)
#define K1B ((NN + 7) / 8)                 // k1 blocks inside merged kernel
#define HISTB ((ET + 127) / 128)           // hist blocks inside merged kernel

// ---------------- scratch (static device globals; no allocation) -------------
__device__ __align__(16) float g_asrc[NN * NH];
__device__ __align__(16) float g_adst[NN * NH];
__device__ __align__(16) float g_ax[(size_t)NN * AXP]; // aggregated x per head (19.2 MB)
__device__ int   g_cnt[NN];     // zero-initialized; re-zeroed by k_offsets each call
__device__ int   g_off[NN];
__device__ int   g_qend[NN];
__device__ int   g_cur[NN];
__device__ int   g_total;       // zero-initialized; re-zeroed by k_scatter each call
__device__ int   g_ssrc[ET];
__device__ __align__(16) uint4 g_wp[ET];   // 8 x fp16 unnormalized exp weights (7.2 MB)
__device__ float g_h2[NN];
__device__ float g_a2s[NN];
__device__ float g_a2d[NN];

__device__ __forceinline__ float lrelu(float v) { return v > 0.f ? v : 0.2f * v; }
__device__ __forceinline__ float4 f4fma(float a, float4 v, float4 acc) {
    acc.x = fmaf(a, v.x, acc.x); acc.y = fmaf(a, v.y, acc.y);
    acc.z = fmaf(a, v.z, acc.z); acc.w = fmaf(a, v.w, acc.w); return acc;
}
__device__ __forceinline__ float f4dot(float4 a, float4 b) {
    return a.x * b.x + a.y * b.y + a.z * b.z + a.w * b.w;
}
__device__ __forceinline__ int edge_at(const void* ei, int idx, int is64) {
    return is64 ? (int)((const long long*)ei)[idx] : ((const int*)ei)[idx];
}
// block-local edge dtype detection (int32 vs int64), broadcast via smem.
__device__ __forceinline__ int detect_is64(const void* ei, int nNodes, int* sflag) {
    if (threadIdx.x == 0) {
        const long long* p = (const long long*)ei;
        int ok = 1;
#pragma unroll 1
        for (int k = 0; k < 8; k++) {
            long long v = p[k];
            if (v < 0 || v >= nNodes) { ok = 0; break; }
        }
        *sflag = ok;
    }
    __syncthreads();
    return *sflag;
}

// ---------------- K1: attention scores | degree histogram (merged) -----------
__global__ void k1_hist(const float* __restrict__ x, const float* __restrict__ W1,
                        const float* __restrict__ as1, const float* __restrict__ ad1,
                        const void* __restrict__ ei, int nNodes, int nE) {
    __shared__ float sx[8][FIN];
    __shared__ int sflag;
    int t = threadIdx.x;
    if (blockIdx.x >= K1B) {                 // ---- histogram role ----
        int is64 = detect_is64(ei, nNodes, &sflag);
        int i = (blockIdx.x - K1B) * 128 + t;
        int tot = nE + nNodes;
        if (i >= tot) return;
        int d = (i < nE) ? edge_at(ei, nE + i, is64) : (i - nE);
        if ((unsigned)d >= (unsigned)nNodes) return;
        atomicAdd(&g_cnt[d], 1);
        return;
    }
    // ---- k1 role: h = x@W1 in registers only, for the attention dots ----
    int nb = blockIdx.x * 8;
    if (t < 8 * FIN) {
        int ni = t / FIN, k = t % FIN;
        int n = nb + ni;
        sx[ni][k] = (n < nNodes) ? x[(size_t)n * FIN + k] : 0.f;
    }
    float4 w[FIN];
#pragma unroll
    for (int k = 0; k < FIN; k++) w[k] = ((const float4*)W1)[k * 128 + t];
    float4 a4 = ((const float4*)as1)[t];
    float4 d4 = ((const float4*)ad1)[t];
    __syncthreads();
    int head = t >> 4;  // 16 threads per head
#pragma unroll 1
    for (int ni = 0; ni < 8; ni++) {
        int n = nb + ni;
        if (n >= nNodes) break;
        float4 acc = {0.f, 0.f, 0.f, 0.f};
#pragma unroll
        for (int k = 0; k < FIN; k++) acc = f4fma(sx[ni][k], w[k], acc);
        float ps = f4dot(acc, a4);
        float pd = f4dot(acc, d4);
#pragma unroll
        for (int o = 8; o >= 1; o >>= 1) {
            ps += __shfl_xor_sync(0xffffffffu, ps, o);
            pd += __shfl_xor_sync(0xffffffffu, pd, o);
        }
        if ((t & 15) == 0) {
            g_asrc[n * NH + head] = ps;
            g_adst[n * NH + head] = pd;
        }
    }
}

// ---------------- K2: offsets via warp-aggregated atomic bump ----------------
__global__ void k_offsets(int nNodes) {
    int n = blockIdx.x * blockDim.x + threadIdx.x;
    int lane = threadIdx.x & 31;
    int c = (n < nNodes) ? g_cnt[n] : 0;
    int incl = c;
#pragma unroll
    for (int o = 1; o < 32; o <<= 1) {
        int v = __shfl_up_sync(0xffffffffu, incl, o);
        if (lane >= o) incl += v;
    }
    int wtot = __shfl_sync(0xffffffffu, incl, 31);
    int base = 0;
    if (lane == 31) base = atomicAdd(&g_total, wtot);
    base = __shfl_sync(0xffffffffu, base, 31);
    if (n < nNodes) {
        int start = base + incl - c;
        g_off[n]  = start;
        g_qend[n] = start + c;
        g_cur[n]  = start;
        g_cnt[n]  = 0;                       // reset for next replay
    }
}

// ---------------- K3: scatter sorted edges + packed fp16 exp scores ----------
__global__ void k_scatter(const void* __restrict__ ei, int nE, int nNodes) {
    __shared__ int sflag;
    int is64 = detect_is64(ei, nNodes, &sflag);
    if (blockIdx.x == 0 && threadIdx.x == 0) g_total = 0;   // reset for next replay
    int i = blockIdx.x * blockDim.x + threadIdx.x;
    int tot = nE + nNodes;
    if (i >= tot) return;
    int s, d;
    if (i < nE) { s = edge_at(ei, i, is64); d = edge_at(ei, nE + i, is64); }
    else        { s = d = i - nE; }
    if ((unsigned)d >= (unsigned)nNodes || (unsigned)s >= (unsigned)nNodes) return;
    int pos = atomicAdd(&g_cur[d], 1);
    g_ssrc[pos] = s;
    float4 a0 = ((const float4*)&g_asrc[s * NH])[0];
    float4 a1 = ((const float4*)&g_asrc[s * NH])[1];
    float4 d0 = ((const float4*)&g_adst[d * NH])[0];
    float4 d1 = ((const float4*)&g_adst[d * NH])[1];
    float4 e0, e1;
    e0.x = __expf(lrelu(a0.x + d0.x)); e0.y = __expf(lrelu(a0.y + d0.y));
    e0.z = __expf(lrelu(a0.z + d0.z)); e0.w = __expf(lrelu(a0.w + d0.w));
    e1.x = __expf(lrelu(a1.x + d1.x)); e1.y = __expf(lrelu(a1.y + d1.y));
    e1.z = __expf(lrelu(a1.z + d1.z)); e1.w = __expf(lrelu(a1.w + d1.w));
    union { __half2 h2[4]; uint4 u; } pk;
    pk.h2[0] = __floats2half2_rn(e0.x, e0.y);   // wp.x = heads 0,1
    pk.h2[1] = __floats2half2_rn(e0.z, e0.w);   // wp.y = heads 2,3
    pk.h2[2] = __floats2half2_rn(e1.x, e1.y);   // wp.z = heads 4,5
    pk.h2[3] = __floats2half2_rn(e1.z, e1.w);   // wp.w = heads 6,7
    g_wp[pos] = pk.u;
}

// ---------------- K4: input-space aggregation (2 threads per node) -----------
// By linearity: sum_e w_e * (x[src_e] @ W1) = (sum_e w_e * x[src_e]) @ W1.
// Thread (2n+half) owns node n, heads [4*half, 4*half+4): 44 fp32 accumulators.
// Output padded to 12 floats/head for aligned float4 reads in k_trans.
__global__ void __launch_bounds__(128)
k_agg_x(const float* __restrict__ x, int nNodes) {
    int tid = blockIdx.x * blockDim.x + threadIdx.x;
    int n = tid >> 1;
    int half = tid & 1;
    if (n >= nNodes) return;
    int p = g_off[n], q = g_qend[n];

    float ax[4][FIN];
    float sw[4];
#pragma unroll
    for (int h = 0; h < 4; h++) {
        sw[h] = 0.f;
#pragma unroll
        for (int d = 0; d < FIN; d++) ax[h][d] = 0.f;
    }
#pragma unroll 1
    for (int i = p; i < q; i++) {
        uint4 wp = g_wp[i];
        int sn = g_ssrc[i];
        unsigned u0 = half ? wp.z : wp.x;
        unsigned u1 = half ? wp.w : wp.y;
        float2 f0 = __half22float2(*(__half2*)&u0);
        float2 f1 = __half22float2(*(__half2*)&u1);
        float w[4] = {f0.x, f0.y, f1.x, f1.y};
        const float* xr = x + (size_t)sn * FIN;
        float xv[FIN];
#pragma unroll
        for (int d = 0; d < FIN; d++) xv[d] = __ldg(xr + d);
#pragma unroll
        for (int h = 0; h < 4; h++) {
            sw[h] += w[h];
#pragma unroll
            for (int d = 0; d < FIN; d++) ax[h][d] = fmaf(w[h], xv[d], ax[h][d]);
        }
    }
    float* out = &g_ax[(size_t)n * AXP + half * 48];   // 4 heads x 12 floats
#pragma unroll
    for (int h = 0; h < 4; h++) {
        float inv = 1.f / (sw[h] + 1e-16f);
#pragma unroll
        for (int d = 0; d < FIN; d++) out[h * 12 + d] = ax[h][d] * inv;
    }
}

// ---------------- K5: transform with W1 RESIDENT IN REGISTERS ----------------
// Thread t permanently owns channels c0=t and c1=t+256 (heads t>>6 and
// (t>>6)+4): their W1 columns (22 floats), b1, W2 stay in registers for ALL
// nodes -> zero per-node W1 traffic. Per node, the 88 aggregated values are
// read as 6 broadcast LDG.128 (head is warp-uniform: lanes 32w..32w+31 lie in
// one 64-channel run). 4-node batches amortize the reduction syncs.
__global__ void __launch_bounds__(256)
k_trans(const float* __restrict__ W1, const float* __restrict__ b1,
        const float* __restrict__ W2,
        const float* __restrict__ as2, const float* __restrict__ ad2,
        int nNodes) {
    __shared__ float swsum[4][8];
    int t = threadIdx.x;
    int lane = t & 31, wid = t >> 5;
    int c0 = t, c1 = t + 256;
    int h0 = t >> 6;                 // head of c0 (warp-uniform); head of c1 = h0+4
    float w1a[FIN], w1b[FIN];
#pragma unroll
    for (int d = 0; d < FIN; d++) {
        w1a[d] = __ldg(W1 + d * HC + c0);
        w1b[d] = __ldg(W1 + d * HC + c1);
    }
    float bA = __ldg(b1 + c0), bB = __ldg(b1 + c1);
    float w2A = __ldg(W2 + c0), w2B = __ldg(W2 + c1);
    float s2 = as2[0], d2 = ad2[0];

#pragma unroll 1
    for (int nb = blockIdx.x * 4; nb < nNodes; nb += gridDim.x * 4) {
        float part[4];
#pragma unroll
        for (int j = 0; j < 4; j++) {
            int n = nb + j;
            if (n < nNodes) {
                const float4* pa = (const float4*)&g_ax[(size_t)n * AXP + h0 * 12];
                const float4* pb = (const float4*)&g_ax[(size_t)n * AXP + 48 + h0 * 12];
                float4 A0 = __ldg(pa), A1 = __ldg(pa + 1), A2 = __ldg(pa + 2);
                float4 B0 = __ldg(pb), B1 = __ldg(pb + 1), B2 = __ldg(pb + 2);
                float aV[FIN] = {A0.x, A0.y, A0.z, A0.w, A1.x, A1.y, A1.z, A1.w,
                                 A2.x, A2.y, A2.z};
                float bV[FIN] = {B0.x, B0.y, B0.z, B0.w, B1.x, B1.y, B1.z, B1.w,
                                 B2.x, B2.y, B2.z};
                float u0 = bA, u1 = bB;
#pragma unroll
                for (int d = 0; d < FIN; d++) {
                    u0 = fmaf(aV[d], w1a[d], u0);
                    u1 = fmaf(bV[d], w1b[d], u1);
                }
                u0 = u0 > 0.f ? u0 : __expf(u0) - 1.f;   // ELU
                u1 = u1 > 0.f ? u1 : __expf(u1) - 1.f;
                part[j] = fmaf(u0, w2A, u1 * w2B);
            } else part[j] = 0.f;
        }
#pragma unroll
        for (int o = 16; o; o >>= 1)
#pragma unroll
            for (int j = 0; j < 4; j++)
                part[j] += __shfl_xor_sync(0xffffffffu, part[j], o);
        if (lane == 0)
#pragma unroll
            for (int j = 0; j < 4; j++) swsum[j][wid] = part[j];
        __syncthreads();
        if (wid == 0) {
            int j = lane >> 3, k = lane & 7;
            float v = swsum[j][k];
            v += __shfl_xor_sync(0xffffffffu, v, 4);
            v += __shfl_xor_sync(0xffffffffu, v, 2);
            v += __shfl_xor_sync(0xffffffffu, v, 1);
            int n = nb + j;
            if (k == 0 && n < nNodes) {
                g_h2[n]  = v;
                g_a2s[n] = v * s2;
                g_a2d[n] = v * d2;
            }
        }
        __syncthreads();
    }
}

// ---------------- K6: layer-2 attention (warp per node, single pass) ---------
__global__ void k_l2(float* __restrict__ out, const float* __restrict__ b2, int nNodes) {
    int n = (blockIdx.x * blockDim.x + threadIdx.x) >> 5;
    int lane = threadIdx.x & 31;
    if (n >= nNodes) return;
    int p = g_off[n], q = g_qend[n];
    float ad = g_a2d[n];
    float sum = 0.f, acc = 0.f;
    for (int i = p + lane; i < q; i += 32) {
        int sn = g_ssrc[i];
        float v = __expf(lrelu(g_a2s[sn] + ad));
        sum += v;
        acc = fmaf(v, g_h2[sn], acc);
    }
#pragma unroll
    for (int o = 16; o; o >>= 1) {
        sum += __shfl_xor_sync(0xffffffffu, sum, o);
        acc += __shfl_xor_sync(0xffffffffu, acc, o);
    }
    if (lane == 0) out[n] = acc / (sum + 1e-16f) + b2[0];
}

// ---------------- launch -----------------------------------------------------
extern "C" void kernel_launch(void* const* d_in, const int* in_sizes, int n_in,
                              void* d_out, int out_size) {
    const float* x   = (const float*)d_in[0];
    const void*  ei  = d_in[1];
    const float* W1  = (const float*)d_in[2];
    const float* as1 = (const float*)d_in[3];
    const float* ad1 = (const float*)d_in[4];
    const float* b1  = (const float*)d_in[5];
    const float* W2  = (const float*)d_in[6];
    const float* as2 = (const float*)d_in[7];
    const float* ad2 = (const float*)d_in[8];
    const float* b2  = (const float*)d_in[9];

    int nN = in_sizes[0] / FIN;   // 50000
    int nE = in_sizes[1] / 2;     // 400000
    int tot = nN + nE;

    k1_hist  <<<K1B + HISTB, 128>>>(x, W1, as1, ad1, ei, nN, nE);
    k_offsets<<<(nN + 255) / 256, 256>>>(nN);
    k_scatter<<<(tot + 255) / 256, 256>>>(ei, nE, nN);
    k_agg_x  <<<(2 * nN + 127) / 128, 128>>>(x, nN);
    k_trans  <<<592, 256>>>(W1, b1, W2, as2, ad2, nN);
    k_l2     <<<(nN + 7) / 8, 256>>>((float*)d_out, b2, nN);
}

// round 14
// speedup vs baseline: 1.1558x; 1.0472x over previous
#include <cuda_runtime.h>
#include <cuda_fp16.h>
#include <math.h>

#define NN 50000          // nodes
#define NE 400000         // edges (without self loops)
#define ET (NN + NE)      // total edges incl. self loops
#define NH 8              // heads
#define HC 512            // heads * channels
#define FIN 11            // input features
#define AXP 96            // padded aggregated row: 8 heads x 12 (11 + pad)
#define NPB 32            // nodes per k1-role block
#define K1B ((NN + NPB - 1) / NPB)         // k1 blocks inside merged kernel
#define HISTB ((ET + 127) / 128)           // hist blocks inside merged kernel

// ---------------- scratch (static device globals; no allocation) -------------
__device__ __align__(16) float g_asrc[NN * NH];
__device__ __align__(16) float g_adst[NN * NH];
__device__ __align__(16) float g_ax[(size_t)NN * AXP]; // aggregated x per head (19.2 MB)
__device__ int   g_cnt[NN];     // zero-initialized; re-zeroed by k_offsets each call
__device__ int   g_off[NN];
__device__ int   g_qend[NN];
__device__ int   g_cur[NN];
__device__ int   g_total;       // zero-initialized; re-zeroed by k_scatter each call
__device__ int   g_ssrc[ET];
__device__ float g_h2[NN];
__device__ float g_a2s[NN];
__device__ float g_a2d[NN];

__device__ __forceinline__ float lrelu(float v) { return v > 0.f ? v : 0.2f * v; }
__device__ __forceinline__ float4 f4fma(float a, float4 v, float4 acc) {
    acc.x = fmaf(a, v.x, acc.x); acc.y = fmaf(a, v.y, acc.y);
    acc.z = fmaf(a, v.z, acc.z); acc.w = fmaf(a, v.w, acc.w); return acc;
}
__device__ __forceinline__ float f4dot(float4 a, float4 b) {
    return a.x * b.x + a.y * b.y + a.z * b.z + a.w * b.w;
}
__device__ __forceinline__ int edge_at(const void* ei, int idx, int is64) {
    return is64 ? (int)((const long long*)ei)[idx] : ((const int*)ei)[idx];
}
// block-local edge dtype detection (int32 vs int64), broadcast via smem.
__device__ __forceinline__ int detect_is64(const void* ei, int nNodes, int* sflag) {
    if (threadIdx.x == 0) {
        const long long* p = (const long long*)ei;
        int ok = 1;
#pragma unroll 1
        for (int k = 0; k < 8; k++) {
            long long v = p[k];
            if (v < 0 || v >= nNodes) { ok = 0; break; }
        }
        *sflag = ok;
    }
    __syncthreads();
    return *sflag;
}

// ---------------- K1: attention scores | degree histogram (merged) -----------
// k1 role: 32 nodes/block to amortize the per-thread W1 register load (4x less
// W1 L2 traffic than 8 nodes/block). h = x@W1 lives in registers only.
__global__ void k1_hist(const float* __restrict__ x, const float* __restrict__ W1,
                        const float* __restrict__ as1, const float* __restrict__ ad1,
                        const void* __restrict__ ei, int nNodes, int nE) {
    __shared__ float sx[NPB][FIN];
    __shared__ int sflag;
    int t = threadIdx.x;
    if (blockIdx.x >= K1B) {                 // ---- histogram role ----
        int is64 = detect_is64(ei, nNodes, &sflag);
        int i = (blockIdx.x - K1B) * 128 + t;
        int tot = nE + nNodes;
        if (i >= tot) return;
        int d = (i < nE) ? edge_at(ei, nE + i, is64) : (i - nE);
        if ((unsigned)d >= (unsigned)nNodes) return;
        atomicAdd(&g_cnt[d], 1);
        return;
    }
    // ---- k1 role ----
    int nb = blockIdx.x * NPB;
    for (int i = t; i < NPB * FIN; i += 128) {
        int ni = i / FIN, k = i % FIN;
        int n = nb + ni;
        sx[ni][k] = (n < nNodes) ? x[(size_t)n * FIN + k] : 0.f;
    }
    float4 w[FIN];
#pragma unroll
    for (int k = 0; k < FIN; k++) w[k] = ((const float4*)W1)[k * 128 + t];
    float4 a4 = ((const float4*)as1)[t];
    float4 d4 = ((const float4*)ad1)[t];
    __syncthreads();
    int head = t >> 4;  // 16 threads per head
#pragma unroll 1
    for (int ni = 0; ni < NPB; ni++) {
        int n = nb + ni;
        if (n >= nNodes) break;
        float4 acc = {0.f, 0.f, 0.f, 0.f};
#pragma unroll
        for (int k = 0; k < FIN; k++) acc = f4fma(sx[ni][k], w[k], acc);
        float ps = f4dot(acc, a4);
        float pd = f4dot(acc, d4);
#pragma unroll
        for (int o = 8; o >= 1; o >>= 1) {
            ps += __shfl_xor_sync(0xffffffffu, ps, o);
            pd += __shfl_xor_sync(0xffffffffu, pd, o);
        }
        if ((t & 15) == 0) {
            g_asrc[n * NH + head] = ps;
            g_adst[n * NH + head] = pd;
        }
    }
}

// ---------------- K2: offsets via warp-aggregated atomic bump ----------------
__global__ void k_offsets(int nNodes) {
    int n = blockIdx.x * blockDim.x + threadIdx.x;
    int lane = threadIdx.x & 31;
    int c = (n < nNodes) ? g_cnt[n] : 0;
    int incl = c;
#pragma unroll
    for (int o = 1; o < 32; o <<= 1) {
        int v = __shfl_up_sync(0xffffffffu, incl, o);
        if (lane >= o) incl += v;
    }
    int wtot = __shfl_sync(0xffffffffu, incl, 31);
    int base = 0;
    if (lane == 31) base = atomicAdd(&g_total, wtot);
    base = __shfl_sync(0xffffffffu, base, 31);
    if (n < nNodes) {
        int start = base + incl - c;
        g_off[n]  = start;
        g_qend[n] = start + c;
        g_cur[n]  = start;
        g_cnt[n]  = 0;                       // reset for next replay
    }
}

// ---------------- K3: scatter sorted edge src indices (index-only) -----------
// Scores moved to k_agg_x (same 16B load there, asrc instead of packed wp),
// so scatter is just: read edge, atomic bump, 4B write.
__global__ void k_scatter(const void* __restrict__ ei, int nE, int nNodes) {
    __shared__ int sflag;
    int is64 = detect_is64(ei, nNodes, &sflag);
    if (blockIdx.x == 0 && threadIdx.x == 0) g_total = 0;   // reset for next replay
    int i = blockIdx.x * blockDim.x + threadIdx.x;
    int tot = nE + nNodes;
    if (i >= tot) return;
    int s, d;
    if (i < nE) { s = edge_at(ei, i, is64); d = edge_at(ei, nE + i, is64); }
    else        { s = d = i - nE; }
    if ((unsigned)d >= (unsigned)nNodes || (unsigned)s >= (unsigned)nNodes) return;
    int pos = atomicAdd(&g_cur[d], 1);
    g_ssrc[pos] = s;
}

// ---------------- K4: input-space aggregation (4 threads per node) -----------
// By linearity: sum_e w_e * (x[src_e] @ W1) = (sum_e w_e * x[src_e]) @ W1.
// Thread (4n+qt) owns node n, heads {2qt, 2qt+1}: 22 fp32 accumulators.
// Edge weights computed inline (fp32 exact): w = exp(lrelu(asrc[sn]+adst[n])).
// 200K threads / ~45 regs vs R12's 100K / 72 -> double the latency-hiding.
__global__ void __launch_bounds__(256)
k_agg_x(const float* __restrict__ x, int nNodes) {
    int tid = blockIdx.x * blockDim.x + threadIdx.x;
    int n = tid >> 2;
    int qt = tid & 3;                 // owns heads 2qt, 2qt+1
    if (n >= nNodes) return;
    int p = g_off[n], q = g_qend[n];
    float2 ad = *(const float2*)&g_adst[n * NH + 2 * qt];

    float ax0[FIN], ax1[FIN];
    float sw0 = 0.f, sw1 = 0.f;
#pragma unroll
    for (int d = 0; d < FIN; d++) { ax0[d] = 0.f; ax1[d] = 0.f; }
#pragma unroll 1
    for (int i = p; i < q; i++) {
        int sn = g_ssrc[i];
        float2 as = *(const float2*)&g_asrc[sn * NH + 2 * qt];
        float w0 = __expf(lrelu(as.x + ad.x));
        float w1 = __expf(lrelu(as.y + ad.y));
        const float* xr = x + (size_t)sn * FIN;
        float xv[FIN];
#pragma unroll
        for (int d = 0; d < FIN; d++) xv[d] = __ldg(xr + d);
        sw0 += w0; sw1 += w1;
#pragma unroll
        for (int d = 0; d < FIN; d++) {
            ax0[d] = fmaf(w0, xv[d], ax0[d]);
            ax1[d] = fmaf(w1, xv[d], ax1[d]);
        }
    }
    float inv0 = 1.f / (sw0 + 1e-16f);
    float inv1 = 1.f / (sw1 + 1e-16f);
    float* out = &g_ax[(size_t)n * AXP + qt * 24];   // head h at offset h*12
#pragma unroll
    for (int d = 0; d < FIN; d++) {
        out[d]      = ax0[d] * inv0;
        out[12 + d] = ax1[d] * inv1;
    }
}

// ---------------- K5: transform with W1 RESIDENT IN REGISTERS ----------------
// Thread t permanently owns channels c0=t and c1=t+256 (heads t>>6, (t>>6)+4):
// W1 columns, b1, W2 stay in registers for ALL nodes.
__global__ void __launch_bounds__(256)
k_trans(const float* __restrict__ W1, const float* __restrict__ b1,
        const float* __restrict__ W2,
        const float* __restrict__ as2, const float* __restrict__ ad2,
        int nNodes) {
    __shared__ float swsum[4][8];
    int t = threadIdx.x;
    int lane = t & 31, wid = t >> 5;
    int c0 = t, c1 = t + 256;
    int h0 = t >> 6;                 // head of c0 (warp-uniform); head of c1 = h0+4
    float w1a[FIN], w1b[FIN];
#pragma unroll
    for (int d = 0; d < FIN; d++) {
        w1a[d] = __ldg(W1 + d * HC + c0);
        w1b[d] = __ldg(W1 + d * HC + c1);
    }
    float bA = __ldg(b1 + c0), bB = __ldg(b1 + c1);
    float w2A = __ldg(W2 + c0), w2B = __ldg(W2 + c1);
    float s2 = as2[0], d2 = ad2[0];

#pragma unroll 1
    for (int nb = blockIdx.x * 4; nb < nNodes; nb += gridDim.x * 4) {
        float part[4];
#pragma unroll
        for (int j = 0; j < 4; j++) {
            int n = nb + j;
            if (n < nNodes) {
                const float4* pa = (const float4*)&g_ax[(size_t)n * AXP + h0 * 12];
                const float4* pb = (const float4*)&g_ax[(size_t)n * AXP + 48 + h0 * 12];
                float4 A0 = __ldg(pa), A1 = __ldg(pa + 1), A2 = __ldg(pa + 2);
                float4 B0 = __ldg(pb), B1 = __ldg(pb + 1), B2 = __ldg(pb + 2);
                float aV[FIN] = {A0.x, A0.y, A0.z, A0.w, A1.x, A1.y, A1.z, A1.w,
                                 A2.x, A2.y, A2.z};
                float bV[FIN] = {B0.x, B0.y, B0.z, B0.w, B1.x, B1.y, B1.z, B1.w,
                                 B2.x, B2.y, B2.z};
                float u0 = bA, u1 = bB;
#pragma unroll
                for (int d = 0; d < FIN; d++) {
                    u0 = fmaf(aV[d], w1a[d], u0);
                    u1 = fmaf(bV[d], w1b[d], u1);
                }
                u0 = u0 > 0.f ? u0 : __expf(u0) - 1.f;   // ELU
                u1 = u1 > 0.f ? u1 : __expf(u1) - 1.f;
                part[j] = fmaf(u0, w2A, u1 * w2B);
            } else part[j] = 0.f;
        }
#pragma unroll
        for (int o = 16; o; o >>= 1)
#pragma unroll
            for (int j = 0; j < 4; j++)
                part[j] += __shfl_xor_sync(0xffffffffu, part[j], o);
        if (lane == 0)
#pragma unroll
            for (int j = 0; j < 4; j++) swsum[j][wid] = part[j];
        __syncthreads();
        if (wid == 0) {
            int j = lane >> 3, k = lane & 7;
            float v = swsum[j][k];
            v += __shfl_xor_sync(0xffffffffu, v, 4);
            v += __shfl_xor_sync(0xffffffffu, v, 2);
            v += __shfl_xor_sync(0xffffffffu, v, 1);
            int n = nb + j;
            if (k == 0 && n < nNodes) {
                g_h2[n]  = v;
                g_a2s[n] = v * s2;
                g_a2d[n] = v * d2;
            }
        }
        __syncthreads();
    }
}

// ---------------- K6: layer-2 attention (warp per node, single pass) ---------
__global__ void k_l2(float* __restrict__ out, const float* __restrict__ b2, int nNodes) {
    int n = (blockIdx.x * blockDim.x + threadIdx.x) >> 5;
    int lane = threadIdx.x & 31;
    if (n >= nNodes) return;
    int p = g_off[n], q = g_qend[n];
    float ad = g_a2d[n];
    float sum = 0.f, acc = 0.f;
    for (int i = p + lane; i < q; i += 32) {
        int sn = g_ssrc[i];
        float v = __expf(lrelu(g_a2s[sn] + ad));
        sum += v;
        acc = fmaf(v, g_h2[sn], acc);
    }
#pragma unroll
    for (int o = 16; o; o >>= 1) {
        sum += __shfl_xor_sync(0xffffffffu, sum, o);
        acc += __shfl_xor_sync(0xffffffffu, acc, o);
    }
    if (lane == 0) out[n] = acc / (sum + 1e-16f) + b2[0];
}

// ---------------- launch -----------------------------------------------------
extern "C" void kernel_launch(void* const* d_in, const int* in_sizes, int n_in,
                              void* d_out, int out_size) {
    const float* x   = (const float*)d_in[0];
    const void*  ei  = d_in[1];
    const float* W1  = (const float*)d_in[2];
    const float* as1 = (const float*)d_in[3];
    const float* ad1 = (const float*)d_in[4];
    const float* b1  = (const float*)d_in[5];
    const float* W2  = (const float*)d_in[6];
    const float* as2 = (const float*)d_in[7];
    const float* ad2 = (const float*)d_in[8];
    const float* b2  = (const float*)d_in[9];

    int nN = in_sizes[0] / FIN;   // 50000
    int nE = in_sizes[1] / 2;     // 400000
    int tot = nN + nE;

    k1_hist  <<<K1B + HISTB, 128>>>(x, W1, as1, ad1, ei, nN, nE);
    k_offsets<<<(nN + 255) / 256, 256>>>(nN);
    k_scatter<<<(tot + 255) / 256, 256>>>(ei, nE, nN);
    k_agg_x  <<<(4 * nN + 255) / 256, 256>>>(x, nN);
    k_trans  <<<592, 256>>>(W1, b1, W2, as2, ad2, nN);
    k_l2     <<<(nN + 7) / 8, 256>>>((float*)d_out, b2, nN);
}

// round 15
// speedup vs baseline: 1.5056x; 1.3026x over previous
#include <cuda_runtime.h>
#include <cuda_fp16.h>
#include <math.h>

#define NN 50000          // nodes
#define NE 400000         // edges (without self loops)
#define ET (NN + NE)      // total edges incl. self loops
#define NH 8              // heads
#define HC 512            // heads * channels
#define FIN 11            // input features
#define NPB 32            // nodes per k1-role block
#define K1B ((NN + NPB - 1) / NPB)         // k1 blocks inside merged kernel
#define HISTB ((ET + 127) / 128)           // hist blocks inside merged kernel
#define FNB 64            // nodes per fused agg+trans block
#define SAXS 97           // smem stride per node (96 + 1 pad: conflict-free)

// ---------------- scratch (static device globals; no allocation) -------------
__device__ __align__(16) float g_asrc[NN * NH];
__device__ __align__(16) float g_adst[NN * NH];
__device__ int   g_cnt[NN];     // zero-initialized; re-zeroed by k_offsets each call
__device__ int   g_off[NN];
__device__ int   g_qend[NN];
__device__ int   g_cur[NN];
__device__ int   g_total;       // zero-initialized; re-zeroed by k_scatter each call
__device__ int   g_ssrc[ET];
__device__ float g_h2[NN];
__device__ float g_a2s[NN];
__device__ float g_a2d[NN];

__device__ __forceinline__ float lrelu(float v) { return v > 0.f ? v : 0.2f * v; }
__device__ __forceinline__ float4 f4fma(float a, float4 v, float4 acc) {
    acc.x = fmaf(a, v.x, acc.x); acc.y = fmaf(a, v.y, acc.y);
    acc.z = fmaf(a, v.z, acc.z); acc.w = fmaf(a, v.w, acc.w); return acc;
}
__device__ __forceinline__ float f4dot(float4 a, float4 b) {
    return a.x * b.x + a.y * b.y + a.z * b.z + a.w * b.w;
}
__device__ __forceinline__ int edge_at(const void* ei, int idx, int is64) {
    return is64 ? (int)((const long long*)ei)[idx] : ((const int*)ei)[idx];
}
// block-local edge dtype detection (int32 vs int64), broadcast via smem.
__device__ __forceinline__ int detect_is64(const void* ei, int nNodes, int* sflag) {
    if (threadIdx.x == 0) {
        const long long* p = (const long long*)ei;
        int ok = 1;
#pragma unroll 1
        for (int k = 0; k < 8; k++) {
            long long v = p[k];
            if (v < 0 || v >= nNodes) { ok = 0; break; }
        }
        *sflag = ok;
    }
    __syncthreads();
    return *sflag;
}

// ---------------- K1: attention scores | degree histogram (merged) -----------
__global__ void k1_hist(const float* __restrict__ x, const float* __restrict__ W1,
                        const float* __restrict__ as1, const float* __restrict__ ad1,
                        const void* __restrict__ ei, int nNodes, int nE) {
    __shared__ float sx[NPB][FIN];
    __shared__ int sflag;
    int t = threadIdx.x;
    if (blockIdx.x >= K1B) {                 // ---- histogram role ----
        int is64 = detect_is64(ei, nNodes, &sflag);
        int i = (blockIdx.x - K1B) * 128 + t;
        int tot = nE + nNodes;
        if (i >= tot) return;
        int d = (i < nE) ? edge_at(ei, nE + i, is64) : (i - nE);
        if ((unsigned)d >= (unsigned)nNodes) return;
        atomicAdd(&g_cnt[d], 1);
        return;
    }
    // ---- k1 role: h = x@W1 in registers only, for the attention dots ----
    int nb = blockIdx.x * NPB;
    for (int i = t; i < NPB * FIN; i += 128) {
        int ni = i / FIN, k = i % FIN;
        int n = nb + ni;
        sx[ni][k] = (n < nNodes) ? x[(size_t)n * FIN + k] : 0.f;
    }
    float4 w[FIN];
#pragma unroll
    for (int k = 0; k < FIN; k++) w[k] = ((const float4*)W1)[k * 128 + t];
    float4 a4 = ((const float4*)as1)[t];
    float4 d4 = ((const float4*)ad1)[t];
    __syncthreads();
    int head = t >> 4;  // 16 threads per head
#pragma unroll 1
    for (int ni = 0; ni < NPB; ni++) {
        int n = nb + ni;
        if (n >= nNodes) break;
        float4 acc = {0.f, 0.f, 0.f, 0.f};
#pragma unroll
        for (int k = 0; k < FIN; k++) acc = f4fma(sx[ni][k], w[k], acc);
        float ps = f4dot(acc, a4);
        float pd = f4dot(acc, d4);
#pragma unroll
        for (int o = 8; o >= 1; o >>= 1) {
            ps += __shfl_xor_sync(0xffffffffu, ps, o);
            pd += __shfl_xor_sync(0xffffffffu, pd, o);
        }
        if ((t & 15) == 0) {
            g_asrc[n * NH + head] = ps;
            g_adst[n * NH + head] = pd;
        }
    }
}

// ---------------- K2: offsets via warp-aggregated atomic bump ----------------
__global__ void k_offsets(int nNodes) {
    int n = blockIdx.x * blockDim.x + threadIdx.x;
    int lane = threadIdx.x & 31;
    int c = (n < nNodes) ? g_cnt[n] : 0;
    int incl = c;
#pragma unroll
    for (int o = 1; o < 32; o <<= 1) {
        int v = __shfl_up_sync(0xffffffffu, incl, o);
        if (lane >= o) incl += v;
    }
    int wtot = __shfl_sync(0xffffffffu, incl, 31);
    int base = 0;
    if (lane == 31) base = atomicAdd(&g_total, wtot);
    base = __shfl_sync(0xffffffffu, base, 31);
    if (n < nNodes) {
        int start = base + incl - c;
        g_off[n]  = start;
        g_qend[n] = start + c;
        g_cur[n]  = start;
        g_cnt[n]  = 0;                       // reset for next replay
    }
}

// ---------------- K3: scatter sorted edge src indices (index-only) -----------
__global__ void k_scatter(const void* __restrict__ ei, int nE, int nNodes) {
    __shared__ int sflag;
    int is64 = detect_is64(ei, nNodes, &sflag);
    if (blockIdx.x == 0 && threadIdx.x == 0) g_total = 0;   // reset for next replay
    int i = blockIdx.x * blockDim.x + threadIdx.x;
    int tot = nE + nNodes;
    if (i >= tot) return;
    int s, d;
    if (i < nE) { s = edge_at(ei, i, is64); d = edge_at(ei, nE + i, is64); }
    else        { s = d = i - nE; }
    if ((unsigned)d >= (unsigned)nNodes || (unsigned)s >= (unsigned)nNodes) return;
    int pos = atomicAdd(&g_cur[d], 1);
    g_ssrc[pos] = s;
}

// ---------------- K4: FUSED aggregation + transform --------------------------
// Phase 1 (4 threads/node, 64 nodes/block): input-space softmax aggregation
//   ax[head] = sum_e w_e x[src_e] / sum_e w_e, w = exp(lrelu(asrc+adst)),
//   written to smem (stride 97: phase-1 write banks (nl+24qt+d)&31 are all
//   distinct across a warp; phase-2 reads are warp-uniform broadcasts).
// Phase 2 (thread t owns channels t and t+256; W1 columns in REGISTERS):
//   u_c = ELU(ax[head(c)].W1[:,c] + b1_c); h2 = sum_c u_c W2_c.
__global__ void __launch_bounds__(256)
k_agg_trans(const float* __restrict__ x, const float* __restrict__ W1,
            const float* __restrict__ b1, const float* __restrict__ W2,
            const float* __restrict__ as2, const float* __restrict__ ad2,
            int nNodes) {
    __shared__ float sax[FNB * SAXS];    // 24.8 KB
    __shared__ float swsum[4][8];
    int t = threadIdx.x;
    int nb = blockIdx.x * FNB;

    // ---- phase 1: aggregate (node nl = t>>2, heads {2qt, 2qt+1}) ----
    {
        int nl = t >> 2, qt = t & 3;
        int n = nb + nl;
        if (n < nNodes) {
            int p = g_off[n], q = g_qend[n];
            float2 ad = *(const float2*)&g_adst[n * NH + 2 * qt];
            float ax0[FIN], ax1[FIN];
            float sw0 = 0.f, sw1 = 0.f;
#pragma unroll
            for (int d = 0; d < FIN; d++) { ax0[d] = 0.f; ax1[d] = 0.f; }
            int i = p;
#pragma unroll 1
            for (; i + 2 <= q; i += 2) {           // unroll x2 (latency-bound loop)
                int sn0 = g_ssrc[i], sn1 = g_ssrc[i + 1];
                float2 as0 = *(const float2*)&g_asrc[sn0 * NH + 2 * qt];
                float2 as1 = *(const float2*)&g_asrc[sn1 * NH + 2 * qt];
                const float* xr0 = x + (size_t)sn0 * FIN;
                const float* xr1 = x + (size_t)sn1 * FIN;
                float xv0[FIN], xv1[FIN];
#pragma unroll
                for (int d = 0; d < FIN; d++) { xv0[d] = __ldg(xr0 + d); xv1[d] = __ldg(xr1 + d); }
                float w00 = __expf(lrelu(as0.x + ad.x));
                float w01 = __expf(lrelu(as0.y + ad.y));
                float w10 = __expf(lrelu(as1.x + ad.x));
                float w11 = __expf(lrelu(as1.y + ad.y));
                sw0 += w00 + w10; sw1 += w01 + w11;
#pragma unroll
                for (int d = 0; d < FIN; d++) {
                    ax0[d] = fmaf(w00, xv0[d], fmaf(w10, xv1[d], ax0[d]));
                    ax1[d] = fmaf(w01, xv0[d], fmaf(w11, xv1[d], ax1[d]));
                }
            }
            if (i < q) {
                int sn = g_ssrc[i];
                float2 as = *(const float2*)&g_asrc[sn * NH + 2 * qt];
                const float* xr = x + (size_t)sn * FIN;
                float w0 = __expf(lrelu(as.x + ad.x));
                float w1 = __expf(lrelu(as.y + ad.y));
                sw0 += w0; sw1 += w1;
#pragma unroll
                for (int d = 0; d < FIN; d++) {
                    float xv = __ldg(xr + d);
                    ax0[d] = fmaf(w0, xv, ax0[d]);
                    ax1[d] = fmaf(w1, xv, ax1[d]);
                }
            }
            float inv0 = 1.f / (sw0 + 1e-16f);
            float inv1 = 1.f / (sw1 + 1e-16f);
            float* out = &sax[nl * SAXS + qt * 24];   // head h at offset h*12
#pragma unroll
            for (int d = 0; d < FIN; d++) {
                out[d]      = ax0[d] * inv0;
                out[12 + d] = ax1[d] * inv1;
            }
        }
    }

    // ---- load W1 columns into registers (overlaps the barrier wait) ----
    int c0 = t, c1 = t + 256;
    int h0 = t >> 6;                 // head of c0 (warp-uniform); head of c1 = h0+4
    float w1a[FIN], w1b[FIN];
#pragma unroll
    for (int d = 0; d < FIN; d++) {
        w1a[d] = __ldg(W1 + d * HC + c0);
        w1b[d] = __ldg(W1 + d * HC + c1);
    }
    float bA = __ldg(b1 + c0), bB = __ldg(b1 + c1);
    float w2A = __ldg(W2 + c0), w2B = __ldg(W2 + c1);
    float s2 = as2[0], d2 = ad2[0];
    __syncthreads();

    // ---- phase 2: transform 64 nodes, 4 at a time ----
    int lane = t & 31, wid = t >> 5;
#pragma unroll 1
    for (int g = 0; g < FNB; g += 4) {
        float part[4];
#pragma unroll
        for (int j = 0; j < 4; j++) {
            int n = nb + g + j;
            if (n < nNodes) {
                const float* pa = &sax[(g + j) * SAXS + h0 * 12];       // broadcast
                const float* pb = &sax[(g + j) * SAXS + (h0 + 4) * 12]; // broadcast
                float u0 = bA, u1 = bB;
#pragma unroll
                for (int d = 0; d < FIN; d++) {
                    u0 = fmaf(pa[d], w1a[d], u0);
                    u1 = fmaf(pb[d], w1b[d], u1);
                }
                u0 = u0 > 0.f ? u0 : __expf(u0) - 1.f;   // ELU
                u1 = u1 > 0.f ? u1 : __expf(u1) - 1.f;
                part[j] = fmaf(u0, w2A, u1 * w2B);
            } else part[j] = 0.f;
        }
#pragma unroll
        for (int o = 16; o; o >>= 1)
#pragma unroll
            for (int j = 0; j < 4; j++)
                part[j] += __shfl_xor_sync(0xffffffffu, part[j], o);
        if (lane == 0)
#pragma unroll
            for (int j = 0; j < 4; j++) swsum[j][wid] = part[j];
        __syncthreads();
        if (wid == 0) {
            int j = lane >> 3, k = lane & 7;
            float v = swsum[j][k];
            v += __shfl_xor_sync(0xffffffffu, v, 4);
            v += __shfl_xor_sync(0xffffffffu, v, 2);
            v += __shfl_xor_sync(0xffffffffu, v, 1);
            int n = nb + g + j;
            if (k == 0 && n < nNodes) {
                g_h2[n]  = v;
                g_a2s[n] = v * s2;
                g_a2d[n] = v * d2;
            }
        }
        __syncthreads();
    }
}

// ---------------- K5: layer-2 attention (8 threads/node) ---------------------
// Avg degree ~9, so octets waste far fewer lanes than full warps.
__global__ void k_l2(float* __restrict__ out, const float* __restrict__ b2, int nNodes) {
    int tid = blockIdx.x * blockDim.x + threadIdx.x;
    int n = tid >> 3;
    int oct = tid & 7;
    if (n >= nNodes) return;
    int p = g_off[n], q = g_qend[n];
    float ad = g_a2d[n];
    float sum = 0.f, acc = 0.f;
    for (int i = p + oct; i < q; i += 8) {
        int sn = g_ssrc[i];
        float v = __expf(lrelu(g_a2s[sn] + ad));
        sum += v;
        acc = fmaf(v, g_h2[sn], acc);
    }
#pragma unroll
    for (int o = 4; o; o >>= 1) {        // xor-reduce within the octet
        sum += __shfl_xor_sync(0xffffffffu, sum, o);
        acc += __shfl_xor_sync(0xffffffffu, acc, o);
    }
    if (oct == 0) out[n] = acc / (sum + 1e-16f) + b2[0];
}

// ---------------- launch -----------------------------------------------------
extern "C" void kernel_launch(void* const* d_in, const int* in_sizes, int n_in,
                              void* d_out, int out_size) {
    const float* x   = (const float*)d_in[0];
    const void*  ei  = d_in[1];
    const float* W1  = (const float*)d_in[2];
    const float* as1 = (const float*)d_in[3];
    const float* ad1 = (const float*)d_in[4];
    const float* b1  = (const float*)d_in[5];
    const float* W2  = (const float*)d_in[6];
    const float* as2 = (const float*)d_in[7];
    const float* ad2 = (const float*)d_in[8];
    const float* b2  = (const float*)d_in[9];

    int nN = in_sizes[0] / FIN;   // 50000
    int nE = in_sizes[1] / 2;     // 400000
    int tot = nN + nE;

    k1_hist    <<<K1B + HISTB, 128>>>(x, W1, as1, ad1, ei, nN, nE);
    k_offsets  <<<(nN + 255) / 256, 256>>>(nN);
    k_scatter  <<<(tot + 255) / 256, 256>>>(ei, nE, nN);
    k_agg_trans<<<(nN + FNB - 1) / FNB, 256>>>(x, W1, b1, W2, as2, ad2, nN);
    k_l2       <<<(8 * nN + 255) / 256, 256>>>((float*)d_out, b2, nN);
}

// round 16
// speedup vs baseline: 1.5373x; 1.0210x over previous
#include <cuda_runtime.h>
#include <cuda_fp16.h>
#include <math.h>

#define NN 50000          // nodes
#define NE 400000         // edges (without self loops)
#define ET (NN + NE)      // total edges incl. self loops
#define NH 8              // heads
#define HC 512            // heads * channels
#define FIN 11            // input features
#define NPB 32            // nodes per k1-role block
#define K1B ((NN + NPB - 1) / NPB)         // k1 blocks inside merged kernel
#define HISTB ((ET + 127) / 128)           // hist blocks inside merged kernel
#define FNB 64            // nodes per fused agg+trans block
#define SAXS 100          // smem floats per node: 4 pairs x 12 float2 = 96 + pad(4)
                          // stride 400B = 0 mod 16 -> ulonglong2 loads aligned

typedef unsigned long long ull;

// ---------------- scratch (static device globals; no allocation) -------------
__device__ __align__(16) float g_asrc[NN * NH];
__device__ __align__(16) float g_adst[NN * NH];
__device__ int   g_cnt[NN];     // zero-initialized; re-zeroed by k_offsets each call
__device__ int   g_off[NN];
__device__ int   g_qend[NN];
__device__ int   g_cur[NN];
__device__ int   g_total;       // zero-initialized; re-zeroed by k_scatter each call
__device__ int   g_ssrc[ET];
__device__ float g_h2[NN];
__device__ float g_a2s[NN];
__device__ float g_a2d[NN];

__device__ __forceinline__ float lrelu(float v) { return v > 0.f ? v : 0.2f * v; }
__device__ __forceinline__ float4 f4fma(float a, float4 v, float4 acc) {
    acc.x = fmaf(a, v.x, acc.x); acc.y = fmaf(a, v.y, acc.y);
    acc.z = fmaf(a, v.z, acc.z); acc.w = fmaf(a, v.w, acc.w); return acc;
}
__device__ __forceinline__ float f4dot(float4 a, float4 b) {
    return a.x * b.x + a.y * b.y + a.z * b.z + a.w * b.w;
}
__device__ __forceinline__ int edge_at(const void* ei, int idx, int is64) {
    return is64 ? (int)((const long long*)ei)[idx] : ((const int*)ei)[idx];
}
__device__ __forceinline__ int detect_is64(const void* ei, int nNodes, int* sflag) {
    if (threadIdx.x == 0) {
        const long long* p = (const long long*)ei;
        int ok = 1;
#pragma unroll 1
        for (int k = 0; k < 8; k++) {
            long long v = p[k];
            if (v < 0 || v >= nNodes) { ok = 0; break; }
        }
        *sflag = ok;
    }
    __syncthreads();
    return *sflag;
}
__device__ __forceinline__ ull pack2(float lo, float hi) {
    float2 t = make_float2(lo, hi);
    return *(ull*)&t;
}
// packed dual-FMA: acc = v * w + acc, elementwise on (lo,hi) fp32 pairs
#define FFMA2(acc, v, w) \
    asm("fma.rn.f32x2 %0, %1, %2, %0;" : "+l"(acc) : "l"(v), "l"(w))

// ---------------- K1: attention scores | degree histogram (merged) -----------
__global__ void k1_hist(const float* __restrict__ x, const float* __restrict__ W1,
                        const float* __restrict__ as1, const float* __restrict__ ad1,
                        const void* __restrict__ ei, int nNodes, int nE) {
    __shared__ float sx[NPB][FIN];
    __shared__ int sflag;
    int t = threadIdx.x;
    if (blockIdx.x >= K1B) {                 // ---- histogram role ----
        int is64 = detect_is64(ei, nNodes, &sflag);
        int i = (blockIdx.x - K1B) * 128 + t;
        int tot = nE + nNodes;
        if (i >= tot) return;
        int d = (i < nE) ? edge_at(ei, nE + i, is64) : (i - nE);
        if ((unsigned)d >= (unsigned)nNodes) return;
        atomicAdd(&g_cnt[d], 1);
        return;
    }
    // ---- k1 role: h = x@W1 in registers only, for the attention dots ----
    int nb = blockIdx.x * NPB;
    for (int i = t; i < NPB * FIN; i += 128) {
        int ni = i / FIN, k = i % FIN;
        int n = nb + ni;
        sx[ni][k] = (n < nNodes) ? x[(size_t)n * FIN + k] : 0.f;
    }
    float4 w[FIN];
#pragma unroll
    for (int k = 0; k < FIN; k++) w[k] = ((const float4*)W1)[k * 128 + t];
    float4 a4 = ((const float4*)as1)[t];
    float4 d4 = ((const float4*)ad1)[t];
    __syncthreads();
    int head = t >> 4;  // 16 threads per head
#pragma unroll 1
    for (int ni = 0; ni < NPB; ni++) {
        int n = nb + ni;
        if (n >= nNodes) break;
        float4 acc = {0.f, 0.f, 0.f, 0.f};
#pragma unroll
        for (int k = 0; k < FIN; k++) acc = f4fma(sx[ni][k], w[k], acc);
        float ps = f4dot(acc, a4);
        float pd = f4dot(acc, d4);
#pragma unroll
        for (int o = 8; o >= 1; o >>= 1) {
            ps += __shfl_xor_sync(0xffffffffu, ps, o);
            pd += __shfl_xor_sync(0xffffffffu, pd, o);
        }
        if ((t & 15) == 0) {
            g_asrc[n * NH + head] = ps;
            g_adst[n * NH + head] = pd;
        }
    }
}

// ---------------- K2: offsets via warp-aggregated atomic bump ----------------
__global__ void k_offsets(int nNodes) {
    int n = blockIdx.x * blockDim.x + threadIdx.x;
    int lane = threadIdx.x & 31;
    int c = (n < nNodes) ? g_cnt[n] : 0;
    int incl = c;
#pragma unroll
    for (int o = 1; o < 32; o <<= 1) {
        int v = __shfl_up_sync(0xffffffffu, incl, o);
        if (lane >= o) incl += v;
    }
    int wtot = __shfl_sync(0xffffffffu, incl, 31);
    int base = 0;
    if (lane == 31) base = atomicAdd(&g_total, wtot);
    base = __shfl_sync(0xffffffffu, base, 31);
    if (n < nNodes) {
        int start = base + incl - c;
        g_off[n]  = start;
        g_qend[n] = start + c;
        g_cur[n]  = start;
        g_cnt[n]  = 0;                       // reset for next replay
    }
}

// ---------------- K3: scatter sorted edge src indices (index-only) -----------
__global__ void k_scatter(const void* __restrict__ ei, int nE, int nNodes) {
    __shared__ int sflag;
    int is64 = detect_is64(ei, nNodes, &sflag);
    if (blockIdx.x == 0 && threadIdx.x == 0) g_total = 0;   // reset for next replay
    int i = blockIdx.x * blockDim.x + threadIdx.x;
    int tot = nE + nNodes;
    if (i >= tot) return;
    int s, d;
    if (i < nE) { s = edge_at(ei, i, is64); d = edge_at(ei, nE + i, is64); }
    else        { s = d = i - nE; }
    if ((unsigned)d >= (unsigned)nNodes || (unsigned)s >= (unsigned)nNodes) return;
    int pos = atomicAdd(&g_cur[d], 1);
    g_ssrc[pos] = s;
}

// ---------------- K4: FUSED aggregation + transform --------------------------
// Phase 1 (4 threads/node): input-space softmax aggregation. Results stored to
// smem in HEAD-PAIR float2 layout: pair p (p=0..3) holds (head p, head p+4)
// interleaved, so phase 2 can consume them with packed f32x2 FMAs.
// Phase 2 (thread t owns channels t, t+256 = heads h0, h0+4 = pair h0):
// 6 x 16B broadcast LDS + 11 FFMA2 per node (vs 22 LDS + 22 FFMA scalar).
__global__ void __launch_bounds__(256)
k_agg_trans(const float* __restrict__ x, const float* __restrict__ W1,
            const float* __restrict__ b1, const float* __restrict__ W2,
            const float* __restrict__ as2, const float* __restrict__ ad2,
            int nNodes) {
    __shared__ __align__(16) float sax[FNB * SAXS];    // 25.6 KB
    __shared__ float swsum[8][8];
    int t = threadIdx.x;
    int nb = blockIdx.x * FNB;

    // ---- phase 1: aggregate (node nl = t>>2, thread qt owns heads 2qt,2qt+1)
    {
        int nl = t >> 2, qt = t & 3;
        int n = nb + nl;
        if (n < nNodes) {
            int p = g_off[n], q = g_qend[n];
            float2 ad = *(const float2*)&g_adst[n * NH + 2 * qt];
            float ax0[FIN], ax1[FIN];
            float sw0 = 0.f, sw1 = 0.f;
#pragma unroll
            for (int d = 0; d < FIN; d++) { ax0[d] = 0.f; ax1[d] = 0.f; }
            int i = p;
#pragma unroll 1
            for (; i + 2 <= q; i += 2) {
                int sn0 = g_ssrc[i], sn1 = g_ssrc[i + 1];
                float2 as0 = *(const float2*)&g_asrc[sn0 * NH + 2 * qt];
                float2 as1 = *(const float2*)&g_asrc[sn1 * NH + 2 * qt];
                const float* xr0 = x + (size_t)sn0 * FIN;
                const float* xr1 = x + (size_t)sn1 * FIN;
                float xv0[FIN], xv1[FIN];
#pragma unroll
                for (int d = 0; d < FIN; d++) { xv0[d] = __ldg(xr0 + d); xv1[d] = __ldg(xr1 + d); }
                float w00 = __expf(lrelu(as0.x + ad.x));
                float w01 = __expf(lrelu(as0.y + ad.y));
                float w10 = __expf(lrelu(as1.x + ad.x));
                float w11 = __expf(lrelu(as1.y + ad.y));
                sw0 += w00 + w10; sw1 += w01 + w11;
#pragma unroll
                for (int d = 0; d < FIN; d++) {
                    ax0[d] = fmaf(w00, xv0[d], fmaf(w10, xv1[d], ax0[d]));
                    ax1[d] = fmaf(w01, xv0[d], fmaf(w11, xv1[d], ax1[d]));
                }
            }
            if (i < q) {
                int sn = g_ssrc[i];
                float2 as = *(const float2*)&g_asrc[sn * NH + 2 * qt];
                const float* xr = x + (size_t)sn * FIN;
                float w0 = __expf(lrelu(as.x + ad.x));
                float w1 = __expf(lrelu(as.y + ad.y));
                sw0 += w0; sw1 += w1;
#pragma unroll
                for (int d = 0; d < FIN; d++) {
                    float xv = __ldg(xr + d);
                    ax0[d] = fmaf(w0, xv, ax0[d]);
                    ax1[d] = fmaf(w1, xv, ax1[d]);
                }
            }
            float inv0 = 1.f / (sw0 + 1e-16f);
            float inv1 = 1.f / (sw1 + 1e-16f);
            // head h -> pair (h&3), slot (h>>2). Thread qt: heads 2qt, 2qt+1
            // -> pairs 2(qt&1), 2(qt&1)+1, slot qt>>1. Entry d of pair p at
            // float offset p*24 + 2d (+slot).
            int pairA = 2 * (qt & 1), slot = qt >> 1;
            float* outA = &sax[nl * SAXS + pairA * 24 + slot];
            float* outB = outA + 24;
#pragma unroll
            for (int d = 0; d < FIN; d++) {
                outA[2 * d] = ax0[d] * inv0;
                outB[2 * d] = ax1[d] * inv1;
            }
        }
    }

    // ---- pack W1 column pairs into registers (overlaps the barrier wait) ----
    int c0 = t, c1 = t + 256;
    int h0 = t >> 6;                 // head of c0 (warp-uniform); head of c1 = h0+4
    ull wpk[FIN];
#pragma unroll
    for (int d = 0; d < FIN; d++)
        wpk[d] = pack2(__ldg(W1 + d * HC + c0), __ldg(W1 + d * HC + c1));
    ull bpk = pack2(__ldg(b1 + c0), __ldg(b1 + c1));
    float w2A = __ldg(W2 + c0), w2B = __ldg(W2 + c1);
    float s2 = as2[0], d2 = ad2[0];
    __syncthreads();

    // ---- phase 2: transform 64 nodes, 8 per reduction batch ----
    int lane = t & 31, wid = t >> 5;
#pragma unroll 1
    for (int g = 0; g < FNB; g += 8) {
        float part[8];
#pragma unroll
        for (int j = 0; j < 8; j++) {
            int n = nb + g + j;
            if (n < nNodes) {
                // pair h0 of node g+j: 12 float2 = 96B, 16B-aligned
                const ulonglong2* pp =
                    (const ulonglong2*)&sax[(g + j) * SAXS + h0 * 24];
                ull acc = bpk;
                ulonglong2 q0 = pp[0], q1 = pp[1], q2 = pp[2], q3 = pp[3], q4 = pp[4];
                ull q5 = ((const ull*)pp)[10];
                FFMA2(acc, q0.x, wpk[0]);  FFMA2(acc, q0.y, wpk[1]);
                FFMA2(acc, q1.x, wpk[2]);  FFMA2(acc, q1.y, wpk[3]);
                FFMA2(acc, q2.x, wpk[4]);  FFMA2(acc, q2.y, wpk[5]);
                FFMA2(acc, q3.x, wpk[6]);  FFMA2(acc, q3.y, wpk[7]);
                FFMA2(acc, q4.x, wpk[8]);  FFMA2(acc, q4.y, wpk[9]);
                FFMA2(acc, q5,   wpk[10]);
                float2 u = *(float2*)&acc;
                u.x = u.x > 0.f ? u.x : __expf(u.x) - 1.f;   // ELU
                u.y = u.y > 0.f ? u.y : __expf(u.y) - 1.f;
                part[j] = fmaf(u.x, w2A, u.y * w2B);
            } else part[j] = 0.f;
        }
#pragma unroll
        for (int o = 16; o; o >>= 1)
#pragma unroll
            for (int j = 0; j < 8; j++)
                part[j] += __shfl_xor_sync(0xffffffffu, part[j], o);
        if (lane == 0)
#pragma unroll
            for (int j = 0; j < 8; j++) swsum[j][wid] = part[j];
        __syncthreads();
        if (wid == 0) {
            int j = lane >> 2, k = lane & 3;      // 4 lanes per node
            float v = swsum[j][k] + swsum[j][k + 4];
            v += __shfl_xor_sync(0xffffffffu, v, 2);
            v += __shfl_xor_sync(0xffffffffu, v, 1);
            int n = nb + g + j;
            if (k == 0 && n < nNodes) {
                g_h2[n]  = v;
                g_a2s[n] = v * s2;
                g_a2d[n] = v * d2;
            }
        }
        __syncthreads();
    }
}

// ---------------- K5: layer-2 attention (8 threads/node) ---------------------
__global__ void k_l2(float* __restrict__ out, const float* __restrict__ b2, int nNodes) {
    int tid = blockIdx.x * blockDim.x + threadIdx.x;
    int n = tid >> 3;
    int oct = tid & 7;
    if (n >= nNodes) return;
    int p = g_off[n], q = g_qend[n];
    float ad = g_a2d[n];
    float sum = 0.f, acc = 0.f;
    for (int i = p + oct; i < q; i += 8) {
        int sn = g_ssrc[i];
        float v = __expf(lrelu(g_a2s[sn] + ad));
        sum += v;
        acc = fmaf(v, g_h2[sn], acc);
    }
#pragma unroll
    for (int o = 4; o; o >>= 1) {
        sum += __shfl_xor_sync(0xffffffffu, sum, o);
        acc += __shfl_xor_sync(0xffffffffu, acc, o);
    }
    if (oct == 0) out[n] = acc / (sum + 1e-16f) + b2[0];
}

// ---------------- launch -----------------------------------------------------
extern "C" void kernel_launch(void* const* d_in, const int* in_sizes, int n_in,
                              void* d_out, int out_size) {
    const float* x   = (const float*)d_in[0];
    const void*  ei  = d_in[1];
    const float* W1  = (const float*)d_in[2];
    const float* as1 = (const float*)d_in[3];
    const float* ad1 = (const float*)d_in[4];
    const float* b1  = (const float*)d_in[5];
    const float* W2  = (const float*)d_in[6];
    const float* as2 = (const float*)d_in[7];
    const float* ad2 = (const float*)d_in[8];
    const float* b2  = (const float*)d_in[9];

    int nN = in_sizes[0] / FIN;   // 50000
    int nE = in_sizes[1] / 2;     // 400000
    int tot = nN + nE;

    k1_hist    <<<K1B + HISTB, 128>>>(x, W1, as1, ad1, ei, nN, nE);
    k_offsets  <<<(nN + 255) / 256, 256>>>(nN);
    k_scatter  <<<(tot + 255) / 256, 256>>>(ei, nE, nN);
    k_agg_trans<<<(nN + FNB - 1) / FNB, 256>>>(x, W1, b1, W2, as2, ad2, nN);
    k_l2       <<<(8 * nN + 255) / 256, 256>>>((float*)d_out, b2, nN);
}

// round 17
// speedup vs baseline: 1.5693x; 1.0208x over previous
#include <cuda_runtime.h>
#include <cuda_fp16.h>
#include <math.h>

#define NN 50000          // nodes
#define NE 400000         // edges (without self loops)
#define ET (NN + NE)      // total edges incl. self loops
#define NH 8              // heads
#define HC 512            // heads * channels
#define FIN 11            // input features
#define FPD 12            // padded x row (48B, 16B-aligned)
#define NPB 32            // nodes per k1-role block
#define K1B ((NN + NPB - 1) / NPB)         // k1 blocks inside merged kernel
#define HISTB ((ET + 127) / 128)           // hist blocks inside merged kernel
#define XCB ((NN * FPD + 127) / 128)       // x-pad copy blocks
#define FNB 64            // nodes per fused agg+trans block
#define SAXS 100          // smem floats per node: 4 pairs x 12 float2 = 96 + pad(4)

typedef unsigned long long ull;

// ---------------- scratch (static device globals; no allocation) -------------
__device__ __align__(16) float g_asrc[NN * NH];
__device__ __align__(16) float g_adst[NN * NH];
__device__ __align__(16) float g_xp[NN * FPD];   // padded x rows (2.4 MB)
__device__ int   g_cnt[NN];     // zero-initialized; re-zeroed by k_offsets each call
__device__ int   g_off[NN];
__device__ int   g_qend[NN];
__device__ int   g_cur[NN];
__device__ int   g_total;       // zero-initialized; re-zeroed by k_scatter each call
__device__ int   g_ssrc[ET];
__device__ float g_h2[NN];
__device__ float g_a2s[NN];
__device__ float g_a2d[NN];

__device__ __forceinline__ float lrelu(float v) { return v > 0.f ? v : 0.2f * v; }
__device__ __forceinline__ float4 f4fma(float a, float4 v, float4 acc) {
    acc.x = fmaf(a, v.x, acc.x); acc.y = fmaf(a, v.y, acc.y);
    acc.z = fmaf(a, v.z, acc.z); acc.w = fmaf(a, v.w, acc.w); return acc;
}
__device__ __forceinline__ float f4dot(float4 a, float4 b) {
    return a.x * b.x + a.y * b.y + a.z * b.z + a.w * b.w;
}
__device__ __forceinline__ int edge_at(const void* ei, int idx, int is64) {
    return is64 ? (int)((const long long*)ei)[idx] : ((const int*)ei)[idx];
}
__device__ __forceinline__ int detect_is64(const void* ei, int nNodes, int* sflag) {
    if (threadIdx.x == 0) {
        const long long* p = (const long long*)ei;
        int ok = 1;
#pragma unroll 1
        for (int k = 0; k < 8; k++) {
            long long v = p[k];
            if (v < 0 || v >= nNodes) { ok = 0; break; }
        }
        *sflag = ok;
    }
    __syncthreads();
    return *sflag;
}
__device__ __forceinline__ ull pack2(float lo, float hi) {
    float2 t = make_float2(lo, hi);
    return *(ull*)&t;
}
#define FFMA2(acc, v, w) \
    asm("fma.rn.f32x2 %0, %1, %2, %0;" : "+l"(acc) : "l"(v), "l"(w))

// ---------------- K1: attention scores | histogram | x-pad (3 roles) ---------
__global__ void k1_hist(const float* __restrict__ x, const float* __restrict__ W1,
                        const float* __restrict__ as1, const float* __restrict__ ad1,
                        const void* __restrict__ ei, int nNodes, int nE) {
    __shared__ float sx[NPB][FIN];
    __shared__ int sflag;
    int t = threadIdx.x;
    if (blockIdx.x >= K1B + HISTB) {         // ---- x-pad role ----
        int i = (blockIdx.x - K1B - HISTB) * 128 + t;
        if (i < nNodes * FPD) {
            int n = i / FPD, d = i - n * FPD;
            g_xp[i] = (d < FIN) ? x[(size_t)n * FIN + d] : 0.f;
        }
        return;
    }
    if (blockIdx.x >= K1B) {                 // ---- histogram role ----
        int is64 = detect_is64(ei, nNodes, &sflag);
        int i = (blockIdx.x - K1B) * 128 + t;
        int tot = nE + nNodes;
        if (i >= tot) return;
        int d = (i < nE) ? edge_at(ei, nE + i, is64) : (i - nE);
        if ((unsigned)d >= (unsigned)nNodes) return;
        atomicAdd(&g_cnt[d], 1);
        return;
    }
    // ---- k1 role: h = x@W1 in registers only, for the attention dots ----
    int nb = blockIdx.x * NPB;
    for (int i = t; i < NPB * FIN; i += 128) {
        int ni = i / FIN, k = i % FIN;
        int n = nb + ni;
        sx[ni][k] = (n < nNodes) ? x[(size_t)n * FIN + k] : 0.f;
    }
    float4 w[FIN];
#pragma unroll
    for (int k = 0; k < FIN; k++) w[k] = ((const float4*)W1)[k * 128 + t];
    float4 a4 = ((const float4*)as1)[t];
    float4 d4 = ((const float4*)ad1)[t];
    __syncthreads();
    int head = t >> 4;  // 16 threads per head
#pragma unroll 1
    for (int ni = 0; ni < NPB; ni++) {
        int n = nb + ni;
        if (n >= nNodes) break;
        float4 acc = {0.f, 0.f, 0.f, 0.f};
#pragma unroll
        for (int k = 0; k < FIN; k++) acc = f4fma(sx[ni][k], w[k], acc);
        float ps = f4dot(acc, a4);
        float pd = f4dot(acc, d4);
#pragma unroll
        for (int o = 8; o >= 1; o >>= 1) {
            ps += __shfl_xor_sync(0xffffffffu, ps, o);
            pd += __shfl_xor_sync(0xffffffffu, pd, o);
        }
        if ((t & 15) == 0) {
            g_asrc[n * NH + head] = ps;
            g_adst[n * NH + head] = pd;
        }
    }
}

// ---------------- K2: offsets via warp-aggregated atomic bump ----------------
__global__ void k_offsets(int nNodes) {
    int n = blockIdx.x * blockDim.x + threadIdx.x;
    int lane = threadIdx.x & 31;
    int c = (n < nNodes) ? g_cnt[n] : 0;
    int incl = c;
#pragma unroll
    for (int o = 1; o < 32; o <<= 1) {
        int v = __shfl_up_sync(0xffffffffu, incl, o);
        if (lane >= o) incl += v;
    }
    int wtot = __shfl_sync(0xffffffffu, incl, 31);
    int base = 0;
    if (lane == 31) base = atomicAdd(&g_total, wtot);
    base = __shfl_sync(0xffffffffu, base, 31);
    if (n < nNodes) {
        int start = base + incl - c;
        g_off[n]  = start;
        g_qend[n] = start + c;
        g_cur[n]  = start;
        g_cnt[n]  = 0;                       // reset for next replay
    }
}

// ---------------- K3: scatter sorted edge src indices (index-only) -----------
__global__ void k_scatter(const void* __restrict__ ei, int nE, int nNodes) {
    __shared__ int sflag;
    int is64 = detect_is64(ei, nNodes, &sflag);
    if (blockIdx.x == 0 && threadIdx.x == 0) g_total = 0;   // reset for next replay
    int i = blockIdx.x * blockDim.x + threadIdx.x;
    int tot = nE + nNodes;
    if (i >= tot) return;
    int s, d;
    if (i < nE) { s = edge_at(ei, i, is64); d = edge_at(ei, nE + i, is64); }
    else        { s = d = i - nE; }
    if ((unsigned)d >= (unsigned)nNodes || (unsigned)s >= (unsigned)nNodes) return;
    int pos = atomicAdd(&g_cur[d], 1);
    g_ssrc[pos] = s;
}

// ---------------- K4: FUSED aggregation + transform --------------------------
// Phase 1 (4 threads/node): input-space softmax aggregation, x rows loaded as
// 3 x LDG.128 from padded g_xp (3 L1 lines/row vs 11 scalar loads before).
// Phase 2: thread t owns channels (t, t+256) = head pair h0; packed f32x2 FMAs.
__global__ void __launch_bounds__(256)
k_agg_trans(const float* __restrict__ W1,
            const float* __restrict__ b1, const float* __restrict__ W2,
            const float* __restrict__ as2, const float* __restrict__ ad2,
            int nNodes) {
    __shared__ __align__(16) float sax[FNB * SAXS];    // 25.6 KB
    __shared__ float swsum[8][8];
    int t = threadIdx.x;
    int nb = blockIdx.x * FNB;

    // ---- phase 1: aggregate (node nl = t>>2, thread qt owns heads 2qt,2qt+1)
    {
        int nl = t >> 2, qt = t & 3;
        int n = nb + nl;
        if (n < nNodes) {
            int p = g_off[n], q = g_qend[n];
            float2 ad = *(const float2*)&g_adst[n * NH + 2 * qt];
            float ax0[FIN], ax1[FIN];
            float sw0 = 0.f, sw1 = 0.f;
#pragma unroll
            for (int d = 0; d < FIN; d++) { ax0[d] = 0.f; ax1[d] = 0.f; }
            int i = p;
#pragma unroll 1
            for (; i + 2 <= q; i += 2) {
                int sn0 = g_ssrc[i], sn1 = g_ssrc[i + 1];
                float2 as0 = *(const float2*)&g_asrc[sn0 * NH + 2 * qt];
                float2 as1 = *(const float2*)&g_asrc[sn1 * NH + 2 * qt];
                const float4* xr0 = (const float4*)&g_xp[sn0 * FPD];
                const float4* xr1 = (const float4*)&g_xp[sn1 * FPD];
                float4 A0 = __ldg(xr0), A1 = __ldg(xr0 + 1), A2 = __ldg(xr0 + 2);
                float4 B0 = __ldg(xr1), B1 = __ldg(xr1 + 1), B2 = __ldg(xr1 + 2);
                float xv0[FIN] = {A0.x, A0.y, A0.z, A0.w, A1.x, A1.y, A1.z, A1.w,
                                  A2.x, A2.y, A2.z};
                float xv1[FIN] = {B0.x, B0.y, B0.z, B0.w, B1.x, B1.y, B1.z, B1.w,
                                  B2.x, B2.y, B2.z};
                float w00 = __expf(lrelu(as0.x + ad.x));
                float w01 = __expf(lrelu(as0.y + ad.y));
                float w10 = __expf(lrelu(as1.x + ad.x));
                float w11 = __expf(lrelu(as1.y + ad.y));
                sw0 += w00 + w10; sw1 += w01 + w11;
#pragma unroll
                for (int d = 0; d < FIN; d++) {
                    ax0[d] = fmaf(w00, xv0[d], fmaf(w10, xv1[d], ax0[d]));
                    ax1[d] = fmaf(w01, xv0[d], fmaf(w11, xv1[d], ax1[d]));
                }
            }
            if (i < q) {
                int sn = g_ssrc[i];
                float2 as = *(const float2*)&g_asrc[sn * NH + 2 * qt];
                const float4* xr = (const float4*)&g_xp[sn * FPD];
                float4 A0 = __ldg(xr), A1 = __ldg(xr + 1), A2 = __ldg(xr + 2);
                float xv[FIN] = {A0.x, A0.y, A0.z, A0.w, A1.x, A1.y, A1.z, A1.w,
                                 A2.x, A2.y, A2.z};
                float w0 = __expf(lrelu(as.x + ad.x));
                float w1 = __expf(lrelu(as.y + ad.y));
                sw0 += w0; sw1 += w1;
#pragma unroll
                for (int d = 0; d < FIN; d++) {
                    ax0[d] = fmaf(w0, xv[d], ax0[d]);
                    ax1[d] = fmaf(w1, xv[d], ax1[d]);
                }
            }
            float inv0 = 1.f / (sw0 + 1e-16f);
            float inv1 = 1.f / (sw1 + 1e-16f);
            // head h -> pair (h&3), slot (h>>2); thread qt: pairs 2(qt&1)(+1),
            // slot qt>>1; entry d of pair p at float offset p*24 + 2d + slot.
            int pairA = 2 * (qt & 1), slot = qt >> 1;
            float* outA = &sax[nl * SAXS + pairA * 24 + slot];
            float* outB = outA + 24;
#pragma unroll
            for (int d = 0; d < FIN; d++) {
                outA[2 * d] = ax0[d] * inv0;
                outB[2 * d] = ax1[d] * inv1;
            }
        }
    }

    // ---- pack W1 column pairs into registers (overlaps the barrier wait) ----
    int c0 = t, c1 = t + 256;
    int h0 = t >> 6;                 // head of c0 (warp-uniform); head of c1 = h0+4
    ull wpk[FIN];
#pragma unroll
    for (int d = 0; d < FIN; d++)
        wpk[d] = pack2(__ldg(W1 + d * HC + c0), __ldg(W1 + d * HC + c1));
    ull bpk = pack2(__ldg(b1 + c0), __ldg(b1 + c1));
    float w2A = __ldg(W2 + c0), w2B = __ldg(W2 + c1);
    float s2 = as2[0], d2 = ad2[0];
    __syncthreads();

    // ---- phase 2: transform 64 nodes, 8 per reduction batch ----
    int lane = t & 31, wid = t >> 5;
#pragma unroll 1
    for (int g = 0; g < FNB; g += 8) {
        float part[8];
#pragma unroll
        for (int j = 0; j < 8; j++) {
            int n = nb + g + j;
            if (n < nNodes) {
                const ulonglong2* pp =
                    (const ulonglong2*)&sax[(g + j) * SAXS + h0 * 24];
                ull acc = bpk;
                ulonglong2 q0 = pp[0], q1 = pp[1], q2 = pp[2], q3 = pp[3], q4 = pp[4];
                ull q5 = ((const ull*)pp)[10];
                FFMA2(acc, q0.x, wpk[0]);  FFMA2(acc, q0.y, wpk[1]);
                FFMA2(acc, q1.x, wpk[2]);  FFMA2(acc, q1.y, wpk[3]);
                FFMA2(acc, q2.x, wpk[4]);  FFMA2(acc, q2.y, wpk[5]);
                FFMA2(acc, q3.x, wpk[6]);  FFMA2(acc, q3.y, wpk[7]);
                FFMA2(acc, q4.x, wpk[8]);  FFMA2(acc, q4.y, wpk[9]);
                FFMA2(acc, q5,   wpk[10]);
                float2 u = *(float2*)&acc;
                u.x = u.x > 0.f ? u.x : __expf(u.x) - 1.f;   // ELU
                u.y = u.y > 0.f ? u.y : __expf(u.y) - 1.f;
                part[j] = fmaf(u.x, w2A, u.y * w2B);
            } else part[j] = 0.f;
        }
#pragma unroll
        for (int o = 16; o; o >>= 1)
#pragma unroll
            for (int j = 0; j < 8; j++)
                part[j] += __shfl_xor_sync(0xffffffffu, part[j], o);
        if (lane == 0)
#pragma unroll
            for (int j = 0; j < 8; j++) swsum[j][wid] = part[j];
        __syncthreads();
        if (wid == 0) {
            int j = lane >> 2, k = lane & 3;      // 4 lanes per node
            float v = swsum[j][k] + swsum[j][k + 4];
            v += __shfl_xor_sync(0xffffffffu, v, 2);
            v += __shfl_xor_sync(0xffffffffu, v, 1);
            int n = nb + g + j;
            if (k == 0 && n < nNodes) {
                g_h2[n]  = v;
                g_a2s[n] = v * s2;
                g_a2d[n] = v * d2;
            }
        }
        __syncthreads();
    }
}

// ---------------- K5: layer-2 attention (8 threads/node) ---------------------
__global__ void k_l2(float* __restrict__ out, const float* __restrict__ b2, int nNodes) {
    int tid = blockIdx.x * blockDim.x + threadIdx.x;
    int n = tid >> 3;
    int oct = tid & 7;
    if (n >= nNodes) return;
    int p = g_off[n], q = g_qend[n];
    float ad = g_a2d[n];
    float sum = 0.f, acc = 0.f;
    for (int i = p + oct; i < q; i += 8) {
        int sn = g_ssrc[i];
        float v = __expf(lrelu(__ldca(&g_a2s[sn]) + ad));
        sum += v;
        acc = fmaf(v, __ldca(&g_h2[sn]), acc);
    }
#pragma unroll
    for (int o = 4; o; o >>= 1) {
        sum += __shfl_xor_sync(0xffffffffu, sum, o);
        acc += __shfl_xor_sync(0xffffffffu, acc, o);
    }
    if (oct == 0) out[n] = acc / (sum + 1e-16f) + b2[0];
}

// ---------------- launch -----------------------------------------------------
extern "C" void kernel_launch(void* const* d_in, const int* in_sizes, int n_in,
                              void* d_out, int out_size) {
    const float* x   = (const float*)d_in[0];
    const void*  ei  = d_in[1];
    const float* W1  = (const float*)d_in[2];
    const float* as1 = (const float*)d_in[3];
    const float* ad1 = (const float*)d_in[4];
    const float* b1  = (const float*)d_in[5];
    const float* W2  = (const float*)d_in[6];
    const float* as2 = (const float*)d_in[7];
    const float* ad2 = (const float*)d_in[8];
    const float* b2  = (const float*)d_in[9];

    int nN = in_sizes[0] / FIN;   // 50000
    int nE = in_sizes[1] / 2;     // 400000
    int tot = nN + nE;

    k1_hist    <<<K1B + HISTB + XCB, 128>>>(x, W1, as1, ad1, ei, nN, nE);
    k_offsets  <<<(nN + 255) / 256, 256>>>(nN);
    k_scatter  <<<(tot + 255) / 256, 256>>>(ei, nE, nN);
    k_agg_trans<<<(nN + FNB - 1) / FNB, 256>>>(W1, b1, W2, as2, ad2, nN);
    k_l2       <<<(8 * nN + 255) / 256, 256>>>((float*)d_out, b2, nN);
}